// round 13
// baseline (speedup 1.0000x reference)
#include <cuda_runtime.h>
#include <cuda_bf16.h>
#include <cstdint>

// ---------------------------------------------------------------------------
// RGCN forward (R9 structure + agg1/layer2 half-pipelining):
//   h = leaky_relu(feature @ w_in + b_in)       gemm_in (64-row tiles)
//   CSR build on side stream (overlapped with gemm_in)
//   layer1 GEMM -> y1/root1 (buf0)
//   agg1(half0) -> [layer2 GEMM(half0) on s2 || agg1(half1) on main]
//   layer2 GEMM(half1) -> y2/root2 (buf1; avoids WAR with agg1 reads of buf0)
//   agg2(from buf1) + final GEMV fused
// ---------------------------------------------------------------------------

#define NMAX 50176
#define DIN  768
#define H    128
#define LEAKY_SLOPE 0.01f
#define KBKT (2 * NMAX)
#define NBLK (KBKT / 1024)
#define EMAX (1 << 20)

// ------------------------------ device scratch ------------------------------
__device__ __align__(16) float g_y[(size_t)2 * NMAX * H];      // layer-1 y
__device__ __align__(16) float g_root[(size_t)NMAX * H];       // layer-1 root
__device__ __align__(16) float g_y2[(size_t)2 * NMAX * H];     // layer-2 y
__device__ __align__(16) float g_root2[(size_t)NMAX * H];      // layer-2 root
__device__ int g_idx32;

__device__ __align__(16) __nv_bfloat16 g_xh[(size_t)NMAX * H];
__device__ __align__(16) __nv_bfloat16 g_xl[(size_t)NMAX * H];
__device__ __align__(16) __nv_bfloat16 g_win_h[(size_t)DIN * H];   // [k][n]
__device__ __align__(16) __nv_bfloat16 g_win_l[(size_t)DIN * H];
__device__ __align__(16) __nv_bfloat16 g_wl_h[(size_t)3 * H * H];  // [which][k][n]
__device__ __align__(16) __nv_bfloat16 g_wl_l[(size_t)3 * H * H];

// CSR
__device__ int g_deg[KBKT];
__device__ int g_scan[KBKT];
__device__ int g_bsum[NBLK];
__device__ int g_off[KBKT + 1];
__device__ int g_cur[KBKT];
__device__ int g_esrc[EMAX];

// ------------------------------- helpers ------------------------------------
__device__ __forceinline__ uint32_t smem_to_u32(const void* p) {
    uint32_t a;
    asm("{ .reg .u64 t; cvta.to.shared.u64 t, %1; cvt.u32.u64 %0, t; }" : "=r"(a) : "l"(p));
    return a;
}
__device__ __forceinline__ void split2(float a, float b, uint32_t& h, uint32_t& l) {
    __nv_bfloat16 ha = __float2bfloat16(a), hb = __float2bfloat16(b);
    __nv_bfloat16 la = __float2bfloat16(a - __bfloat162float(ha));
    __nv_bfloat16 lb = __float2bfloat16(b - __bfloat162float(hb));
    __nv_bfloat162 hp = __halves2bfloat162(ha, hb);
    __nv_bfloat162 lp = __halves2bfloat162(la, lb);
    h = *reinterpret_cast<uint32_t*>(&hp);
    l = *reinterpret_cast<uint32_t*>(&lp);
}
__device__ __forceinline__ void ldsm_x4(uint32_t (&r)[4], uint32_t addr) {
    asm volatile("ldmatrix.sync.aligned.m8n8.x4.shared.b16 {%0,%1,%2,%3}, [%4];"
                 : "=r"(r[0]), "=r"(r[1]), "=r"(r[2]), "=r"(r[3]) : "r"(addr));
}
__device__ __forceinline__ void ldsm_x4t(uint32_t& r0, uint32_t& r1, uint32_t& r2, uint32_t& r3, uint32_t addr) {
    asm volatile("ldmatrix.sync.aligned.m8n8.x4.trans.shared.b16 {%0,%1,%2,%3}, [%4];"
                 : "=r"(r0), "=r"(r1), "=r"(r2), "=r"(r3) : "r"(addr));
}
__device__ __forceinline__ void mma_bf16(float (&d)[4], const uint32_t (&a)[4], const uint32_t (&b)[2]) {
    asm volatile(
        "mma.sync.aligned.m16n8k16.row.col.f32.bf16.bf16.f32 "
        "{%0,%1,%2,%3}, {%4,%5,%6,%7}, {%8,%9}, {%0,%1,%2,%3};"
        : "+f"(d[0]), "+f"(d[1]), "+f"(d[2]), "+f"(d[3])
        : "r"(a[0]), "r"(a[1]), "r"(a[2]), "r"(a[3]), "r"(b[0]), "r"(b[1]));
}

// ---------------- smem layout: gemm_in 64-row tiles ---------------------------
#define I64_AH   0
#define I64_AL   10240
#define I64_BH   20480
#define I64_BL   37888
#define I64_ABUF 5120
#define I64_BBUF 8704
#define I64_SMEM 55296

// ---------------------- smem layout: fused layer GEMM ------------------------
#define FA_H_OFF 0
#define FA_L_OFF 34816
#define FB_OFF   69632
#define FB_BUF   17408
#define FUSED_SMEM 104448

// --------------------------- index dtype handling ---------------------------
__device__ __forceinline__ int ld_idx(const void* p, long long i) {
    if (g_idx32) return ((const int*)p)[i];
    return (int)((const long long*)p)[i];
}

// -------------------- CSR build (detect fused into zero) --------------------
__global__ void zero_deg_detect_kernel(const void* ei, int E) {
    int i = blockIdx.x * blockDim.x + threadIdx.x;
    if (i < KBKT) g_deg[i] = 0;
    if (i == 0) {
        const long long* p = (const long long*)ei;
        int n = E < 256 ? E : 256;
        int is32 = 0;
        for (int k = 0; k < n; k++) {
            long long v = p[k];
            if (v < 0 || v >= (long long)NMAX) { is32 = 1; break; }
        }
        g_idx32 = is32;
    }
}
__global__ void hist_kernel(const void* ei, const void* et, int E) {
    int e = blockIdx.x * blockDim.x + threadIdx.x;
    if (e >= E) return;
    int t   = ld_idx(et, e);
    int dst = ld_idx(ei, (long long)E + e);
    atomicAdd(&g_deg[t * NMAX + dst], 1);
}
__global__ __launch_bounds__(1024) void scan1_kernel() {
    int i = blockIdx.x * 1024 + threadIdx.x;
    int lane = threadIdx.x & 31, w = threadIdx.x >> 5;
    int x = g_deg[i];
    #pragma unroll
    for (int off = 1; off < 32; off <<= 1) {
        int y = __shfl_up_sync(0xFFFFFFFFu, x, off);
        if (lane >= off) x += y;
    }
    __shared__ int wsum[32];
    if (lane == 31) wsum[w] = x;
    __syncthreads();
    if (w == 0) {
        int s = wsum[lane];
        #pragma unroll
        for (int off = 1; off < 32; off <<= 1) {
            int y = __shfl_up_sync(0xFFFFFFFFu, s, off);
            if (lane >= off) s += y;
        }
        wsum[lane] = s;
    }
    __syncthreads();
    if (w > 0) x += wsum[w - 1];
    g_scan[i] = x;
    if (threadIdx.x == 1023) g_bsum[blockIdx.x] = x;
}
__global__ __launch_bounds__(32) void scan2_kernel() {
    int lane = threadIdx.x;
    int carry = 0;
    for (int base = 0; base < NBLK; base += 32) {
        int i = base + lane;
        int x = (i < NBLK) ? g_bsum[i] : 0;
        #pragma unroll
        for (int off = 1; off < 32; off <<= 1) {
            int y = __shfl_up_sync(0xFFFFFFFFu, x, off);
            if (lane >= off) x += y;
        }
        x += carry;
        if (i < NBLK) g_bsum[i] = x;
        carry = __shfl_sync(0xFFFFFFFFu, x, 31);
    }
}
__global__ __launch_bounds__(1024) void scan3_kernel() {
    int i = blockIdx.x * 1024 + threadIdx.x;
    int blk = blockIdx.x;
    int off = g_scan[i] - g_deg[i] + (blk > 0 ? g_bsum[blk - 1] : 0);
    g_off[i] = off;
    g_cur[i] = off;
    if (i == KBKT - 1) g_off[KBKT] = g_bsum[NBLK - 1];
}
__global__ void fill_kernel(const void* ei, const void* et, int E) {
    int e = blockIdx.x * blockDim.x + threadIdx.x;
    if (e >= E) return;
    int src = ld_idx(ei, e);
    int dst = ld_idx(ei, (long long)E + e);
    int t   = ld_idx(et, e);
    int pos = atomicAdd(&g_cur[t * NMAX + dst], 1);
    if (pos >= 0 && pos < EMAX) g_esrc[pos] = src;
}

// -------------------------- weight prep (bf16 split) -------------------------
__global__ void prep_win_kernel(const float* __restrict__ w_in) {
    int idx = blockIdx.x * blockDim.x + threadIdx.x;
    if (idx >= DIN * H) return;
    float v = w_in[idx];
    __nv_bfloat16 h = __float2bfloat16(v);
    g_win_h[idx] = h;
    g_win_l[idx] = __float2bfloat16(v - __bfloat162float(h));
}
__global__ void prep_wl_kernel(const float* __restrict__ w_rel, const float* __restrict__ w_root) {
    int idx = blockIdx.x * blockDim.x + threadIdx.x;
    if (idx >= 3 * H * H) return;
    float v = (idx < 2 * H * H) ? w_rel[idx] : w_root[idx - 2 * H * H];
    __nv_bfloat16 h = __float2bfloat16(v);
    g_wl_h[idx] = h;
    g_wl_l[idx] = __float2bfloat16(v - __bfloat162float(h));
}

// ------------------------------ tile fetch/store -----------------------------
__device__ __forceinline__ void fetch_a_f32_64(const float* __restrict__ A, int block_row, int M,
                                               int k0, float4 (&r)[2]) {
    int tid = threadIdx.x;
    #pragma unroll
    for (int i = 0; i < 2; i++) {
        int idx = tid + i * 256;
        int row = idx >> 3, c4 = idx & 7;
        int gr = block_row + row; if (gr >= M) gr = M - 1;
        r[i] = *reinterpret_cast<const float4*>(A + (size_t)gr * DIN + k0 + c4 * 4);
    }
}
__device__ __forceinline__ void store_a_split_64(char* smem, int buf, const float4 (&r)[2]) {
    int tid = threadIdx.x;
    #pragma unroll
    for (int i = 0; i < 2; i++) {
        int idx = tid + i * 256;
        int row = idx >> 3, c4 = idx & 7;
        uint32_t h0, l0, h1, l1;
        split2(r[i].x, r[i].y, h0, l0);
        split2(r[i].z, r[i].w, h1, l1);
        uint32_t off = (row * 40 + c4 * 4) * 2;
        *reinterpret_cast<uint2*>(smem + I64_AH + buf * I64_ABUF + off) = make_uint2(h0, h1);
        *reinterpret_cast<uint2*>(smem + I64_AL + buf * I64_ABUF + off) = make_uint2(l0, l1);
    }
}
__device__ __forceinline__ void fetch_b(const __nv_bfloat16* __restrict__ bh,
                                        const __nv_bfloat16* __restrict__ bl,
                                        int k0, uint4 (&rh)[2], uint4 (&rl)[2]) {
    int tid = threadIdx.x;
    #pragma unroll
    for (int i = 0; i < 2; i++) {
        int idx = tid + i * 256;
        int row = idx >> 4, col = (idx & 15) * 8;
        size_t so = (size_t)(k0 + row) * H + col;
        rh[i] = *reinterpret_cast<const uint4*>(bh + so);
        rl[i] = *reinterpret_cast<const uint4*>(bl + so);
    }
}
__device__ __forceinline__ void store_b_64(char* smem, int buf, const uint4 (&rh)[2], const uint4 (&rl)[2]) {
    int tid = threadIdx.x;
    #pragma unroll
    for (int i = 0; i < 2; i++) {
        int idx = tid + i * 256;
        int row = idx >> 4, col = (idx & 15) * 8;
        uint32_t off = (row * 136 + col) * 2;
        *reinterpret_cast<uint4*>(smem + I64_BH + buf * I64_BBUF + off) = rh[i];
        *reinterpret_cast<uint4*>(smem + I64_BL + buf * I64_BBUF + off) = rl[i];
    }
}
__device__ __forceinline__ void store_b_fused(char* smem, int buf, const uint4 (&rh)[2], const uint4 (&rl)[2]) {
    int tid = threadIdx.x;
    #pragma unroll
    for (int i = 0; i < 2; i++) {
        int idx = tid + i * 256;
        int row = idx >> 4, col = (idx & 15) * 8;
        uint32_t off = (row * 136 + col) * 2;
        *reinterpret_cast<uint4*>(smem + FB_OFF + buf * FB_BUF + off) = rh[i];
        *reinterpret_cast<uint4*>(smem + FB_OFF + buf * FB_BUF + 8704 + off) = rl[i];
    }
}

// ------------------------------- compute cores --------------------------------
__device__ __forceinline__ void compute_tile_64(uint32_t sbase, int buf, int warp_m, int warp_n,
                                                int lane, float (&acc)[2][4][4]) {
    uint32_t abase_h = sbase + I64_AH + buf * I64_ABUF;
    uint32_t abase_l = sbase + I64_AL + buf * I64_ABUF;
    uint32_t bbase_h = sbase + I64_BH + buf * I64_BBUF;
    uint32_t bbase_l = sbase + I64_BL + buf * I64_BBUF;
    #pragma unroll
    for (int ks = 0; ks < 2; ks++) {
        uint32_t ah[2][4], al[2][4];
        #pragma unroll
        for (int mi = 0; mi < 2; mi++) {
            int m0 = warp_m * 32 + mi * 16;
            uint32_t aoff = ((m0 + (lane & 15)) * 40 + ks * 16 + ((lane >> 4) << 3)) * 2;
            ldsm_x4(ah[mi], abase_h + aoff);
            ldsm_x4(al[mi], abase_l + aoff);
        }
        uint32_t bh[4][2], bl[4][2];
        #pragma unroll
        for (int nb = 0; nb < 2; nb++) {
            int n0 = warp_n * 32 + nb * 16;
            int krow = ks * 16 + ((lane >> 3) & 1) * 8 + (lane & 7);
            int ncol = n0 + (lane >> 4) * 8;
            uint32_t boff = (krow * 136 + ncol) * 2;
            uint32_t r0, r1, r2, r3;
            ldsm_x4t(r0, r1, r2, r3, bbase_h + boff);
            bh[nb * 2][0] = r0; bh[nb * 2][1] = r1; bh[nb * 2 + 1][0] = r2; bh[nb * 2 + 1][1] = r3;
            ldsm_x4t(r0, r1, r2, r3, bbase_l + boff);
            bl[nb * 2][0] = r0; bl[nb * 2][1] = r1; bl[nb * 2 + 1][0] = r2; bl[nb * 2 + 1][1] = r3;
        }
        #pragma unroll
        for (int mi = 0; mi < 2; mi++)
            #pragma unroll
            for (int ni = 0; ni < 4; ni++) {
                mma_bf16(acc[mi][ni], ah[mi], bh[ni]);
                mma_bf16(acc[mi][ni], al[mi], bh[ni]);
                mma_bf16(acc[mi][ni], ah[mi], bl[ni]);
            }
    }
}

__device__ __forceinline__ void compute_tile_fused(uint32_t sbase, int bbuf, int kpos,
                                                   int warp_m, int warp_n,
                                                   int lane, float (&acc)[2][8][4]) {
    uint32_t bbase_h = sbase + FB_OFF + bbuf * FB_BUF;
    uint32_t bbase_l = bbase_h + 8704;
    #pragma unroll
    for (int ks = 0; ks < 2; ks++) {
        int kk = kpos + ks * 16;
        uint32_t ah[2][4], al[2][4];
        #pragma unroll
        for (int mi = 0; mi < 2; mi++) {
            int m0 = warp_m * 32 + mi * 16;
            uint32_t aoff = ((m0 + (lane & 15)) * 136 + kk + ((lane >> 4) << 3)) * 2;
            ldsm_x4(ah[mi], sbase + FA_H_OFF + aoff);
            ldsm_x4(al[mi], sbase + FA_L_OFF + aoff);
        }
        uint32_t bh[8][2], bl[8][2];
        #pragma unroll
        for (int nb = 0; nb < 4; nb++) {
            int n0 = warp_n * 64 + nb * 16;
            int krow = ks * 16 + ((lane >> 3) & 1) * 8 + (lane & 7);
            int ncol = n0 + (lane >> 4) * 8;
            uint32_t boff = (krow * 136 + ncol) * 2;
            uint32_t r0, r1, r2, r3;
            ldsm_x4t(r0, r1, r2, r3, bbase_h + boff);
            bh[nb * 2][0] = r0; bh[nb * 2][1] = r1; bh[nb * 2 + 1][0] = r2; bh[nb * 2 + 1][1] = r3;
            ldsm_x4t(r0, r1, r2, r3, bbase_l + boff);
            bl[nb * 2][0] = r0; bl[nb * 2][1] = r1; bl[nb * 2 + 1][0] = r2; bl[nb * 2 + 1][1] = r3;
        }
        #pragma unroll
        for (int mi = 0; mi < 2; mi++)
            #pragma unroll
            for (int ni = 0; ni < 8; ni++) {
                mma_bf16(acc[mi][ni], ah[mi], bh[ni]);
                mma_bf16(acc[mi][ni], al[mi], bh[ni]);
                mma_bf16(acc[mi][ni], ah[mi], bl[ni]);
            }
    }
}

// ------------------- GEMM 1: feature @ w_in (64-row tiles) --------------------
__global__ __launch_bounds__(256, 2) void gemm_in_mma(
    const float* __restrict__ A, const float* __restrict__ bias, int M)
{
    extern __shared__ char smem[];
    uint32_t sbase = smem_to_u32(smem);
    const int tid = threadIdx.x, lane = tid & 31, wid = tid >> 5;
    const int warp_m = wid & 1, warp_n = wid >> 1;
    const int block_row = blockIdx.x * 64;

    float acc[2][4][4];
    #pragma unroll
    for (int a = 0; a < 2; a++)
        #pragma unroll
        for (int b = 0; b < 4; b++)
            #pragma unroll
            for (int c = 0; c < 4; c++) acc[a][b][c] = 0.f;

    float4 ra[2];
    uint4 rbh[2], rbl[2];
    fetch_a_f32_64(A, block_row, M, 0, ra);
    fetch_b(g_win_h, g_win_l, 0, rbh, rbl);
    store_a_split_64(smem, 0, ra);
    store_b_64(smem, 0, rbh, rbl);
    __syncthreads();

    const int NIT = DIN / 32;  // 24
    #pragma unroll 1
    for (int it = 0; it < NIT; it++) {
        if (it + 1 < NIT) {
            fetch_a_f32_64(A, block_row, M, (it + 1) * 32, ra);
            fetch_b(g_win_h, g_win_l, (it + 1) * 32, rbh, rbl);
        }
        compute_tile_64(sbase, it & 1, warp_m, warp_n, lane, acc);
        if (it + 1 < NIT) {
            store_a_split_64(smem, (it + 1) & 1, ra);
            store_b_64(smem, (it + 1) & 1, rbh, rbl);
        }
        __syncthreads();
    }

    const int g = lane >> 2, t = lane & 3;
    #pragma unroll
    for (int mi = 0; mi < 2; mi++) {
        #pragma unroll
        for (int ni = 0; ni < 4; ni++) {
            int col = warp_n * 32 + ni * 8 + t * 2;
            float b0 = __ldg(&bias[col]), b1 = __ldg(&bias[col + 1]);
            #pragma unroll
            for (int half = 0; half < 2; half++) {
                int row = block_row + warp_m * 32 + mi * 16 + g + half * 8;
                if (row >= M) continue;
                float v0 = acc[mi][ni][half * 2 + 0] + b0;
                float v1 = acc[mi][ni][half * 2 + 1] + b1;
                v0 = v0 >= 0.f ? v0 : LEAKY_SLOPE * v0;
                v1 = v1 >= 0.f ? v1 : LEAKY_SLOPE * v1;
                uint32_t h, l;
                split2(v0, v1, h, l);
                *reinterpret_cast<uint32_t*>(g_xh + (size_t)row * H + col) = h;
                *reinterpret_cast<uint32_t*>(g_xl + (size_t)row * H + col) = l;
            }
        }
    }
}

// --------------- layer GEMM: resident A, 3 weight matrices streamed -----------
// outbuf=0 -> g_y/g_root, outbuf=1 -> g_y2/g_root2. tbase offsets the tile index.
__global__ __launch_bounds__(256, 2) void gemm_layer_fused(
    const float* __restrict__ b_conv, int M, int tbase, int outbuf)
{
    extern __shared__ char smem[];
    uint32_t sbase = smem_to_u32(smem);
    const int tid = threadIdx.x, lane = tid & 31, wid = tid >> 5;
    const int warp_m = wid & 3, warp_n = wid >> 2;
    const int block_row = (tbase + blockIdx.x) * 128;
    float* y_out = outbuf ? g_y2 : g_y;
    float* root_out = outbuf ? g_root2 : g_root;

    #pragma unroll
    for (int i = 0; i < 8; i++) {
        int idx = tid + i * 256;
        int row = idx >> 4, cg = idx & 15;
        size_t so = (size_t)(block_row + row) * H + cg * 8;
        uint32_t off = (row * 136 + cg * 8) * 2;
        *reinterpret_cast<uint4*>(smem + FA_H_OFF + off) = *reinterpret_cast<const uint4*>(g_xh + so);
        *reinterpret_cast<uint4*>(smem + FA_L_OFF + off) = *reinterpret_cast<const uint4*>(g_xl + so);
    }
    uint4 rbh[2], rbl[2];
    fetch_b(g_wl_h, g_wl_l, 0, rbh, rbl);
    store_b_fused(smem, 0, rbh, rbl);
    __syncthreads();

    float acc[2][8][4];
    #pragma unroll
    for (int a = 0; a < 2; a++)
        #pragma unroll
        for (int b = 0; b < 8; b++)
            #pragma unroll
            for (int c = 0; c < 4; c++) acc[a][b][c] = 0.f;

    const int g = lane >> 2, t = lane & 3;

    #pragma unroll 1
    for (int q = 0; q < 12; q++) {
        int which = q >> 2, it = q & 3;
        if (q + 1 < 12) {
            int wn = (q + 1) >> 2, itn = (q + 1) & 3;
            fetch_b(g_wl_h + (size_t)wn * H * H, g_wl_l + (size_t)wn * H * H, itn * 32, rbh, rbl);
        }
        compute_tile_fused(sbase, q & 1, it * 32, warp_m, warp_n, lane, acc);
        if (q + 1 < 12)
            store_b_fused(smem, (q + 1) & 1, rbh, rbl);

        if (it == 3) {
            float* dst = (which < 2) ? (y_out + (size_t)which * NMAX * H) : root_out;
            const bool add_bias = (which == 2);
            #pragma unroll
            for (int mi = 0; mi < 2; mi++) {
                #pragma unroll
                for (int ni = 0; ni < 8; ni++) {
                    int col = warp_n * 64 + ni * 8 + t * 2;
                    float b0 = add_bias ? __ldg(&b_conv[col]) : 0.f;
                    float b1 = add_bias ? __ldg(&b_conv[col + 1]) : 0.f;
                    #pragma unroll
                    for (int half = 0; half < 2; half++) {
                        int row = block_row + warp_m * 32 + mi * 16 + g + half * 8;
                        if (row >= M) continue;
                        float v0 = acc[mi][ni][half * 2 + 0] + b0;
                        float v1 = acc[mi][ni][half * 2 + 1] + b1;
                        *reinterpret_cast<float2*>(dst + (size_t)row * H + col) = make_float2(v0, v1);
                    }
                }
            }
            #pragma unroll
            for (int a = 0; a < 2; a++)
                #pragma unroll
                for (int b = 0; b < 8; b++)
                    #pragma unroll
                    for (int c = 0; c < 4; c++) acc[a][b][c] = 0.f;
        }
        __syncthreads();
    }
}

// ---------------------- fused CSR aggregate + mean + root --------------------
// Processes nodes [nbase, nbase+ncount). srcbuf selects y/root buffers.
// last==0: writes xh/xl. last==1: fuses final GEMV.
__global__ __launch_bounds__(256) void agg_combine_kernel(
    int nbase, int ncount, int M, int srcbuf, int last,
    const float* __restrict__ w_out, const float* __restrict__ b_out,
    float* __restrict__ out)
{
    int wix = (int)(((size_t)blockIdx.x * blockDim.x + threadIdx.x) >> 5);
    int lane = threadIdx.x & 31;
    if (wix >= ncount) return;
    int node = nbase + wix;
    if (node >= M) return;

    const float* rootb = srcbuf ? g_root2 : g_root;
    const float* ybase = srcbuf ? g_y2 : g_y;

    size_t ridx = (size_t)node * (H / 4) + lane;
    float4 o = reinterpret_cast<const float4*>(rootb)[ridx];

    #pragma unroll
    for (int t = 0; t < 2; t++) {
        int beg = g_off[t * NMAX + node];
        int end = g_off[t * NMAX + node + 1];
        int deg = end - beg;
        if (deg <= 0) continue;
        if (deg > EMAX) deg = EMAX;
        end = beg + deg;
        const float* yb = ybase + (size_t)t * NMAX * H;
        float4 s = make_float4(0.f, 0.f, 0.f, 0.f);
        for (int base = beg; base < end; base += 32) {
            int n = min(32, end - base);
            int idx = 0;
            if (lane < n) idx = g_esrc[base + lane];
            int j = 0;
            for (; j + 4 <= n; j += 4) {
                int s0 = __shfl_sync(0xFFFFFFFFu, idx, j);
                int s1 = __shfl_sync(0xFFFFFFFFu, idx, j + 1);
                int s2 = __shfl_sync(0xFFFFFFFFu, idx, j + 2);
                int s3 = __shfl_sync(0xFFFFFFFFu, idx, j + 3);
                float4 v0 = reinterpret_cast<const float4*>(yb + (size_t)s0 * H)[lane];
                float4 v1 = reinterpret_cast<const float4*>(yb + (size_t)s1 * H)[lane];
                float4 v2 = reinterpret_cast<const float4*>(yb + (size_t)s2 * H)[lane];
                float4 v3 = reinterpret_cast<const float4*>(yb + (size_t)s3 * H)[lane];
                s.x += v0.x + v1.x + v2.x + v3.x;
                s.y += v0.y + v1.y + v2.y + v3.y;
                s.z += v0.z + v1.z + v2.z + v3.z;
                s.w += v0.w + v1.w + v2.w + v3.w;
            }
            for (; j < n; j++) {
                int sj = __shfl_sync(0xFFFFFFFFu, idx, j);
                float4 v = reinterpret_cast<const float4*>(yb + (size_t)sj * H)[lane];
                s.x += v.x; s.y += v.y; s.z += v.z; s.w += v.w;
            }
        }
        float inv = 1.f / (float)deg;
        o.x += s.x * inv;
        o.y += s.y * inv;
        o.z += s.z * inv;
        o.w += s.w * inv;
    }

    if (!last) {
        uint32_t h0, l0, h1, l1;
        split2(o.x, o.y, h0, l0);
        split2(o.z, o.w, h1, l1);
        reinterpret_cast<uint2*>(g_xh)[ridx] = make_uint2(h0, h1);
        reinterpret_cast<uint2*>(g_xl)[ridx] = make_uint2(l0, l1);
    } else {
        float s0 = 0.f, s1 = 0.f, s2 = 0.f;
        int r = lane * 4;
        float xc[4] = {o.x, o.y, o.z, o.w};
        #pragma unroll
        for (int c = 0; c < 4; c++) {
            s0 = fmaf(xc[c], __ldg(&w_out[(r + c) * 3 + 0]), s0);
            s1 = fmaf(xc[c], __ldg(&w_out[(r + c) * 3 + 1]), s1);
            s2 = fmaf(xc[c], __ldg(&w_out[(r + c) * 3 + 2]), s2);
        }
        #pragma unroll
        for (int off = 16; off > 0; off >>= 1) {
            s0 += __shfl_xor_sync(0xFFFFFFFFu, s0, off);
            s1 += __shfl_xor_sync(0xFFFFFFFFu, s1, off);
            s2 += __shfl_xor_sync(0xFFFFFFFFu, s2, off);
        }
        if (lane == 0) {
            out[(size_t)node * 3 + 0] = s0 + b_out[0];
            out[(size_t)node * 3 + 1] = s1 + b_out[1];
            out[(size_t)node * 3 + 2] = s2 + b_out[2];
        }
    }
}

// ------------------------------ launch glue -----------------------------------
extern "C" void kernel_launch(void* const* d_in, const int* in_sizes, int n_in,
                              void* d_out, int out_size) {
    const float* feature = (const float*)d_in[0];
    const void*  edge_index = d_in[1];
    const void*  edge_type  = d_in[2];
    const float* w_in   = (const float*)d_in[3];
    const float* b_in   = (const float*)d_in[4];
    const float* w_rel  = (const float*)d_in[5];
    const float* w_root = (const float*)d_in[6];
    const float* b_conv = (const float*)d_in[7];
    const float* w_out  = (const float*)d_in[8];
    const float* b_out  = (const float*)d_in[9];

    const int M = in_sizes[0] / DIN;      // 50000
    const int E = in_sizes[2];            // 600000
    const int tiles64  = (M + 63) / 64;   // 782
    const int tiles128 = (M + 127) / 128; // 391
    const int tilesA = tiles128 / 2;      // 195
    const int tilesB = tiles128 - tilesA; // 196
    const int NH0 = tilesA * 128;         // 24960 nodes in half 0
    const int NH1 = M - NH0;              // 25040 nodes in half 1

    static cudaStream_t s2 = nullptr;
    static cudaEvent_t ev0 = nullptr, ev1 = nullptr, evA0 = nullptr, evA1 = nullptr, evG = nullptr;
    static bool attr_done = false;
    if (!attr_done) {
        cudaFuncSetAttribute(gemm_in_mma, cudaFuncAttributeMaxDynamicSharedMemorySize, I64_SMEM);
        cudaFuncSetAttribute(gemm_layer_fused, cudaFuncAttributeMaxDynamicSharedMemorySize, FUSED_SMEM);
        cudaStreamCreateWithFlags(&s2, cudaStreamNonBlocking);
        cudaEventCreateWithFlags(&ev0, cudaEventDisableTiming);
        cudaEventCreateWithFlags(&ev1, cudaEventDisableTiming);
        cudaEventCreateWithFlags(&evA0, cudaEventDisableTiming);
        cudaEventCreateWithFlags(&evA1, cudaEventDisableTiming);
        cudaEventCreateWithFlags(&evG, cudaEventDisableTiming);
        attr_done = true;
    }

    // Fork side stream for the CSR build
    cudaEventRecord(ev0, 0);
    cudaStreamWaitEvent(s2, ev0, 0);

    // main chain: prep + input GEMM
    prep_win_kernel<<<(DIN * H + 255) / 256, 256>>>(w_in);
    prep_wl_kernel<<<(3 * H * H + 255) / 256, 256>>>(w_rel, w_root);
    zero_deg_detect_kernel<<<(KBKT + 255) / 256, 256, 0, s2>>>(edge_index, E);
    gemm_in_mma<<<tiles64, 256, I64_SMEM>>>(feature, b_in, M);

    // CSR build on side stream
    hist_kernel<<<(E + 255) / 256, 256, 0, s2>>>(edge_index, edge_type, E);
    scan1_kernel<<<NBLK, 1024, 0, s2>>>();
    scan2_kernel<<<1, 32, 0, s2>>>();
    scan3_kernel<<<NBLK, 1024, 0, s2>>>();
    fill_kernel<<<(E + 255) / 256, 256, 0, s2>>>(edge_index, edge_type, E);
    cudaEventRecord(ev1, s2);

    // layer 1 GEMM (all tiles, writes buf0) overlaps CSR tail
    gemm_layer_fused<<<tiles128, 256, FUSED_SMEM>>>(b_conv, M, 0, 0);

    // agg1 half0 (needs CSR + layer1 y)
    cudaStreamWaitEvent(0, ev1, 0);
    agg_combine_kernel<<<(int)(((size_t)NH0 * 32 + 255) / 256), 256>>>(
        0, NH0, M, 0, 0, w_out, b_out, (float*)d_out);
    cudaEventRecord(evA0, 0);

    // agg1 half1 (main) || layer-2 GEMM half0 (s2, reads xh rows of half0 only,
    // writes buf1 so no WAR with agg1's buf0 reads)
    agg_combine_kernel<<<(int)(((size_t)NH1 * 32 + 255) / 256), 256>>>(
        NH0, NH1, M, 0, 0, w_out, b_out, (float*)d_out);
    cudaEventRecord(evA1, 0);

    cudaStreamWaitEvent(s2, evA0, 0);
    gemm_layer_fused<<<tilesA, 256, FUSED_SMEM, s2>>>(b_conv, M, 0, 1);
    cudaStreamWaitEvent(s2, evA1, 0);
    gemm_layer_fused<<<tilesB, 256, FUSED_SMEM, s2>>>(b_conv, M, tilesA, 1);
    cudaEventRecord(evG, s2);

    // agg2 + GEMV (needs all of buf1)
    cudaStreamWaitEvent(0, evG, 0);
    agg_combine_kernel<<<(int)(((size_t)M * 32 + 255) / 256), 256>>>(
        0, M, M, 1, 1, w_out, b_out, (float*)d_out);
}

// round 14
// speedup vs baseline: 1.1154x; 1.1154x over previous
#include <cuda_runtime.h>
#include <cuda_bf16.h>
#include <cstdint>

// ---------------------------------------------------------------------------
// RGCN forward (R9 structure — measured optimum):
//   h = leaky_relu(feature @ w_in + b_in)       gemm_in (64-row tiles)
//   CSR build on side stream (overlapped with gemm_in)
//   per layer: z = x @ [W_r0|W_r1|W_root]       ONE fused mma kernel
//              x' = root + sum_t mean(y_t[src]) high-occupancy warp gather
//   layer 2 agg fuses the final x @ w_out + b_out GEMV.
// ---------------------------------------------------------------------------

#define NMAX 50176
#define DIN  768
#define H    128
#define LEAKY_SLOPE 0.01f
#define KBKT (2 * NMAX)
#define NBLK (KBKT / 1024)
#define EMAX (1 << 20)

// ------------------------------ device scratch ------------------------------
__device__ __align__(16) float g_y[(size_t)2 * NMAX * H];
__device__ __align__(16) float g_root[(size_t)NMAX * H];
__device__ int g_idx32;

__device__ __align__(16) __nv_bfloat16 g_xh[(size_t)NMAX * H];
__device__ __align__(16) __nv_bfloat16 g_xl[(size_t)NMAX * H];
__device__ __align__(16) __nv_bfloat16 g_win_h[(size_t)DIN * H];   // [k][n]
__device__ __align__(16) __nv_bfloat16 g_win_l[(size_t)DIN * H];
__device__ __align__(16) __nv_bfloat16 g_wl_h[(size_t)3 * H * H];  // [which][k][n]
__device__ __align__(16) __nv_bfloat16 g_wl_l[(size_t)3 * H * H];

// CSR
__device__ int g_deg[KBKT];
__device__ int g_scan[KBKT];
__device__ int g_bsum[NBLK];
__device__ int g_off[KBKT + 1];
__device__ int g_cur[KBKT];
__device__ int g_esrc[EMAX];

// ------------------------------- helpers ------------------------------------
__device__ __forceinline__ uint32_t smem_to_u32(const void* p) {
    uint32_t a;
    asm("{ .reg .u64 t; cvta.to.shared.u64 t, %1; cvt.u32.u64 %0, t; }" : "=r"(a) : "l"(p));
    return a;
}
__device__ __forceinline__ void split2(float a, float b, uint32_t& h, uint32_t& l) {
    __nv_bfloat16 ha = __float2bfloat16(a), hb = __float2bfloat16(b);
    __nv_bfloat16 la = __float2bfloat16(a - __bfloat162float(ha));
    __nv_bfloat16 lb = __float2bfloat16(b - __bfloat162float(hb));
    __nv_bfloat162 hp = __halves2bfloat162(ha, hb);
    __nv_bfloat162 lp = __halves2bfloat162(la, lb);
    h = *reinterpret_cast<uint32_t*>(&hp);
    l = *reinterpret_cast<uint32_t*>(&lp);
}
__device__ __forceinline__ void ldsm_x4(uint32_t (&r)[4], uint32_t addr) {
    asm volatile("ldmatrix.sync.aligned.m8n8.x4.shared.b16 {%0,%1,%2,%3}, [%4];"
                 : "=r"(r[0]), "=r"(r[1]), "=r"(r[2]), "=r"(r[3]) : "r"(addr));
}
__device__ __forceinline__ void ldsm_x4t(uint32_t& r0, uint32_t& r1, uint32_t& r2, uint32_t& r3, uint32_t addr) {
    asm volatile("ldmatrix.sync.aligned.m8n8.x4.trans.shared.b16 {%0,%1,%2,%3}, [%4];"
                 : "=r"(r0), "=r"(r1), "=r"(r2), "=r"(r3) : "r"(addr));
}
__device__ __forceinline__ void mma_bf16(float (&d)[4], const uint32_t (&a)[4], const uint32_t (&b)[2]) {
    asm volatile(
        "mma.sync.aligned.m16n8k16.row.col.f32.bf16.bf16.f32 "
        "{%0,%1,%2,%3}, {%4,%5,%6,%7}, {%8,%9}, {%0,%1,%2,%3};"
        : "+f"(d[0]), "+f"(d[1]), "+f"(d[2]), "+f"(d[3])
        : "r"(a[0]), "r"(a[1]), "r"(a[2]), "r"(a[3]), "r"(b[0]), "r"(b[1]));
}

// ---------------- smem layout: gemm_in 64-row tiles ---------------------------
#define I64_AH   0
#define I64_AL   10240
#define I64_BH   20480
#define I64_BL   37888
#define I64_ABUF 5120
#define I64_BBUF 8704
#define I64_SMEM 55296

// ---------------------- smem layout: fused layer GEMM ------------------------
#define FA_H_OFF 0
#define FA_L_OFF 34816
#define FB_OFF   69632
#define FB_BUF   17408
#define FUSED_SMEM 104448

// --------------------------- index dtype handling ---------------------------
__device__ __forceinline__ int ld_idx(const void* p, long long i) {
    if (g_idx32) return ((const int*)p)[i];
    return (int)((const long long*)p)[i];
}

// -------------------- CSR build (detect fused into zero) --------------------
__global__ void zero_deg_detect_kernel(const void* ei, int E) {
    int i = blockIdx.x * blockDim.x + threadIdx.x;
    if (i < KBKT) g_deg[i] = 0;
    if (i == 0) {
        const long long* p = (const long long*)ei;
        int n = E < 256 ? E : 256;
        int is32 = 0;
        for (int k = 0; k < n; k++) {
            long long v = p[k];
            if (v < 0 || v >= (long long)NMAX) { is32 = 1; break; }
        }
        g_idx32 = is32;
    }
}
__global__ void hist_kernel(const void* ei, const void* et, int E) {
    int e = blockIdx.x * blockDim.x + threadIdx.x;
    if (e >= E) return;
    int t   = ld_idx(et, e);
    int dst = ld_idx(ei, (long long)E + e);
    atomicAdd(&g_deg[t * NMAX + dst], 1);
}
__global__ __launch_bounds__(1024) void scan1_kernel() {
    int i = blockIdx.x * 1024 + threadIdx.x;
    int lane = threadIdx.x & 31, w = threadIdx.x >> 5;
    int x = g_deg[i];
    #pragma unroll
    for (int off = 1; off < 32; off <<= 1) {
        int y = __shfl_up_sync(0xFFFFFFFFu, x, off);
        if (lane >= off) x += y;
    }
    __shared__ int wsum[32];
    if (lane == 31) wsum[w] = x;
    __syncthreads();
    if (w == 0) {
        int s = wsum[lane];
        #pragma unroll
        for (int off = 1; off < 32; off <<= 1) {
            int y = __shfl_up_sync(0xFFFFFFFFu, s, off);
            if (lane >= off) s += y;
        }
        wsum[lane] = s;
    }
    __syncthreads();
    if (w > 0) x += wsum[w - 1];
    g_scan[i] = x;
    if (threadIdx.x == 1023) g_bsum[blockIdx.x] = x;
}
__global__ __launch_bounds__(32) void scan2_kernel() {
    int lane = threadIdx.x;
    int carry = 0;
    for (int base = 0; base < NBLK; base += 32) {
        int i = base + lane;
        int x = (i < NBLK) ? g_bsum[i] : 0;
        #pragma unroll
        for (int off = 1; off < 32; off <<= 1) {
            int y = __shfl_up_sync(0xFFFFFFFFu, x, off);
            if (lane >= off) x += y;
        }
        x += carry;
        if (i < NBLK) g_bsum[i] = x;
        carry = __shfl_sync(0xFFFFFFFFu, x, 31);
    }
}
__global__ __launch_bounds__(1024) void scan3_kernel() {
    int i = blockIdx.x * 1024 + threadIdx.x;
    int blk = blockIdx.x;
    int off = g_scan[i] - g_deg[i] + (blk > 0 ? g_bsum[blk - 1] : 0);
    g_off[i] = off;
    g_cur[i] = off;
    if (i == KBKT - 1) g_off[KBKT] = g_bsum[NBLK - 1];
}
__global__ void fill_kernel(const void* ei, const void* et, int E) {
    int e = blockIdx.x * blockDim.x + threadIdx.x;
    if (e >= E) return;
    int src = ld_idx(ei, e);
    int dst = ld_idx(ei, (long long)E + e);
    int t   = ld_idx(et, e);
    int pos = atomicAdd(&g_cur[t * NMAX + dst], 1);
    if (pos >= 0 && pos < EMAX) g_esrc[pos] = src;
}

// ---------------- weight prep (bf16 split), single merged kernel -------------
__global__ void prep_weights_kernel(const float* __restrict__ w_in,
                                    const float* __restrict__ w_rel,
                                    const float* __restrict__ w_root) {
    int idx = blockIdx.x * blockDim.x + threadIdx.x;
    const int NIN = DIN * H;           // 98304
    const int NL  = 3 * H * H;         // 49152
    if (idx < NIN) {
        float v = w_in[idx];
        __nv_bfloat16 h = __float2bfloat16(v);
        g_win_h[idx] = h;
        g_win_l[idx] = __float2bfloat16(v - __bfloat162float(h));
    } else if (idx < NIN + NL) {
        int j = idx - NIN;
        float v = (j < 2 * H * H) ? w_rel[j] : w_root[j - 2 * H * H];
        __nv_bfloat16 h = __float2bfloat16(v);
        g_wl_h[j] = h;
        g_wl_l[j] = __float2bfloat16(v - __bfloat162float(h));
    }
}

// ------------------------------ tile fetch/store -----------------------------
__device__ __forceinline__ void fetch_a_f32_64(const float* __restrict__ A, int block_row, int M,
                                               int k0, float4 (&r)[2]) {
    int tid = threadIdx.x;
    #pragma unroll
    for (int i = 0; i < 2; i++) {
        int idx = tid + i * 256;
        int row = idx >> 3, c4 = idx & 7;
        int gr = block_row + row; if (gr >= M) gr = M - 1;
        r[i] = *reinterpret_cast<const float4*>(A + (size_t)gr * DIN + k0 + c4 * 4);
    }
}
__device__ __forceinline__ void store_a_split_64(char* smem, int buf, const float4 (&r)[2]) {
    int tid = threadIdx.x;
    #pragma unroll
    for (int i = 0; i < 2; i++) {
        int idx = tid + i * 256;
        int row = idx >> 3, c4 = idx & 7;
        uint32_t h0, l0, h1, l1;
        split2(r[i].x, r[i].y, h0, l0);
        split2(r[i].z, r[i].w, h1, l1);
        uint32_t off = (row * 40 + c4 * 4) * 2;
        *reinterpret_cast<uint2*>(smem + I64_AH + buf * I64_ABUF + off) = make_uint2(h0, h1);
        *reinterpret_cast<uint2*>(smem + I64_AL + buf * I64_ABUF + off) = make_uint2(l0, l1);
    }
}
__device__ __forceinline__ void fetch_b(const __nv_bfloat16* __restrict__ bh,
                                        const __nv_bfloat16* __restrict__ bl,
                                        int k0, uint4 (&rh)[2], uint4 (&rl)[2]) {
    int tid = threadIdx.x;
    #pragma unroll
    for (int i = 0; i < 2; i++) {
        int idx = tid + i * 256;
        int row = idx >> 4, col = (idx & 15) * 8;
        size_t so = (size_t)(k0 + row) * H + col;
        rh[i] = *reinterpret_cast<const uint4*>(bh + so);
        rl[i] = *reinterpret_cast<const uint4*>(bl + so);
    }
}
__device__ __forceinline__ void store_b_64(char* smem, int buf, const uint4 (&rh)[2], const uint4 (&rl)[2]) {
    int tid = threadIdx.x;
    #pragma unroll
    for (int i = 0; i < 2; i++) {
        int idx = tid + i * 256;
        int row = idx >> 4, col = (idx & 15) * 8;
        uint32_t off = (row * 136 + col) * 2;
        *reinterpret_cast<uint4*>(smem + I64_BH + buf * I64_BBUF + off) = rh[i];
        *reinterpret_cast<uint4*>(smem + I64_BL + buf * I64_BBUF + off) = rl[i];
    }
}
__device__ __forceinline__ void store_b_fused(char* smem, int buf, const uint4 (&rh)[2], const uint4 (&rl)[2]) {
    int tid = threadIdx.x;
    #pragma unroll
    for (int i = 0; i < 2; i++) {
        int idx = tid + i * 256;
        int row = idx >> 4, col = (idx & 15) * 8;
        uint32_t off = (row * 136 + col) * 2;
        *reinterpret_cast<uint4*>(smem + FB_OFF + buf * FB_BUF + off) = rh[i];
        *reinterpret_cast<uint4*>(smem + FB_OFF + buf * FB_BUF + 8704 + off) = rl[i];
    }
}

// ------------------------------- compute cores --------------------------------
__device__ __forceinline__ void compute_tile_64(uint32_t sbase, int buf, int warp_m, int warp_n,
                                                int lane, float (&acc)[2][4][4]) {
    uint32_t abase_h = sbase + I64_AH + buf * I64_ABUF;
    uint32_t abase_l = sbase + I64_AL + buf * I64_ABUF;
    uint32_t bbase_h = sbase + I64_BH + buf * I64_BBUF;
    uint32_t bbase_l = sbase + I64_BL + buf * I64_BBUF;
    #pragma unroll
    for (int ks = 0; ks < 2; ks++) {
        uint32_t ah[2][4], al[2][4];
        #pragma unroll
        for (int mi = 0; mi < 2; mi++) {
            int m0 = warp_m * 32 + mi * 16;
            uint32_t aoff = ((m0 + (lane & 15)) * 40 + ks * 16 + ((lane >> 4) << 3)) * 2;
            ldsm_x4(ah[mi], abase_h + aoff);
            ldsm_x4(al[mi], abase_l + aoff);
        }
        uint32_t bh[4][2], bl[4][2];
        #pragma unroll
        for (int nb = 0; nb < 2; nb++) {
            int n0 = warp_n * 32 + nb * 16;
            int krow = ks * 16 + ((lane >> 3) & 1) * 8 + (lane & 7);
            int ncol = n0 + (lane >> 4) * 8;
            uint32_t boff = (krow * 136 + ncol) * 2;
            uint32_t r0, r1, r2, r3;
            ldsm_x4t(r0, r1, r2, r3, bbase_h + boff);
            bh[nb * 2][0] = r0; bh[nb * 2][1] = r1; bh[nb * 2 + 1][0] = r2; bh[nb * 2 + 1][1] = r3;
            ldsm_x4t(r0, r1, r2, r3, bbase_l + boff);
            bl[nb * 2][0] = r0; bl[nb * 2][1] = r1; bl[nb * 2 + 1][0] = r2; bl[nb * 2 + 1][1] = r3;
        }
        #pragma unroll
        for (int mi = 0; mi < 2; mi++)
            #pragma unroll
            for (int ni = 0; ni < 4; ni++) {
                mma_bf16(acc[mi][ni], ah[mi], bh[ni]);
                mma_bf16(acc[mi][ni], al[mi], bh[ni]);
                mma_bf16(acc[mi][ni], ah[mi], bl[ni]);
            }
    }
}

__device__ __forceinline__ void compute_tile_fused(uint32_t sbase, int bbuf, int kpos,
                                                   int warp_m, int warp_n,
                                                   int lane, float (&acc)[2][8][4]) {
    uint32_t bbase_h = sbase + FB_OFF + bbuf * FB_BUF;
    uint32_t bbase_l = bbase_h + 8704;
    #pragma unroll
    for (int ks = 0; ks < 2; ks++) {
        int kk = kpos + ks * 16;
        uint32_t ah[2][4], al[2][4];
        #pragma unroll
        for (int mi = 0; mi < 2; mi++) {
            int m0 = warp_m * 32 + mi * 16;
            uint32_t aoff = ((m0 + (lane & 15)) * 136 + kk + ((lane >> 4) << 3)) * 2;
            ldsm_x4(ah[mi], sbase + FA_H_OFF + aoff);
            ldsm_x4(al[mi], sbase + FA_L_OFF + aoff);
        }
        uint32_t bh[8][2], bl[8][2];
        #pragma unroll
        for (int nb = 0; nb < 4; nb++) {
            int n0 = warp_n * 64 + nb * 16;
            int krow = ks * 16 + ((lane >> 3) & 1) * 8 + (lane & 7);
            int ncol = n0 + (lane >> 4) * 8;
            uint32_t boff = (krow * 136 + ncol) * 2;
            uint32_t r0, r1, r2, r3;
            ldsm_x4t(r0, r1, r2, r3, bbase_h + boff);
            bh[nb * 2][0] = r0; bh[nb * 2][1] = r1; bh[nb * 2 + 1][0] = r2; bh[nb * 2 + 1][1] = r3;
            ldsm_x4t(r0, r1, r2, r3, bbase_l + boff);
            bl[nb * 2][0] = r0; bl[nb * 2][1] = r1; bl[nb * 2 + 1][0] = r2; bl[nb * 2 + 1][1] = r3;
        }
        #pragma unroll
        for (int mi = 0; mi < 2; mi++)
            #pragma unroll
            for (int ni = 0; ni < 8; ni++) {
                mma_bf16(acc[mi][ni], ah[mi], bh[ni]);
                mma_bf16(acc[mi][ni], al[mi], bh[ni]);
                mma_bf16(acc[mi][ni], ah[mi], bl[ni]);
            }
    }
}

// ------------------- GEMM 1: feature @ w_in (64-row tiles) --------------------
__global__ __launch_bounds__(256, 2) void gemm_in_mma(
    const float* __restrict__ A, const float* __restrict__ bias, int M)
{
    extern __shared__ char smem[];
    uint32_t sbase = smem_to_u32(smem);
    const int tid = threadIdx.x, lane = tid & 31, wid = tid >> 5;
    const int warp_m = wid & 1, warp_n = wid >> 1;
    const int block_row = blockIdx.x * 64;

    float acc[2][4][4];
    #pragma unroll
    for (int a = 0; a < 2; a++)
        #pragma unroll
        for (int b = 0; b < 4; b++)
            #pragma unroll
            for (int c = 0; c < 4; c++) acc[a][b][c] = 0.f;

    float4 ra[2];
    uint4 rbh[2], rbl[2];
    fetch_a_f32_64(A, block_row, M, 0, ra);
    fetch_b(g_win_h, g_win_l, 0, rbh, rbl);
    store_a_split_64(smem, 0, ra);
    store_b_64(smem, 0, rbh, rbl);
    __syncthreads();

    const int NIT = DIN / 32;  // 24
    #pragma unroll 1
    for (int it = 0; it < NIT; it++) {
        if (it + 1 < NIT) {
            fetch_a_f32_64(A, block_row, M, (it + 1) * 32, ra);
            fetch_b(g_win_h, g_win_l, (it + 1) * 32, rbh, rbl);
        }
        compute_tile_64(sbase, it & 1, warp_m, warp_n, lane, acc);
        if (it + 1 < NIT) {
            store_a_split_64(smem, (it + 1) & 1, ra);
            store_b_64(smem, (it + 1) & 1, rbh, rbl);
        }
        __syncthreads();
    }

    const int g = lane >> 2, t = lane & 3;
    #pragma unroll
    for (int mi = 0; mi < 2; mi++) {
        #pragma unroll
        for (int ni = 0; ni < 4; ni++) {
            int col = warp_n * 32 + ni * 8 + t * 2;
            float b0 = __ldg(&bias[col]), b1 = __ldg(&bias[col + 1]);
            #pragma unroll
            for (int half = 0; half < 2; half++) {
                int row = block_row + warp_m * 32 + mi * 16 + g + half * 8;
                if (row >= M) continue;
                float v0 = acc[mi][ni][half * 2 + 0] + b0;
                float v1 = acc[mi][ni][half * 2 + 1] + b1;
                v0 = v0 >= 0.f ? v0 : LEAKY_SLOPE * v0;
                v1 = v1 >= 0.f ? v1 : LEAKY_SLOPE * v1;
                uint32_t h, l;
                split2(v0, v1, h, l);
                *reinterpret_cast<uint32_t*>(g_xh + (size_t)row * H + col) = h;
                *reinterpret_cast<uint32_t*>(g_xl + (size_t)row * H + col) = l;
            }
        }
    }
}

// --------------- fused layer GEMM: z = x @ {W_r0, W_r1, W_root} --------------
__global__ __launch_bounds__(256, 2) void gemm_layer_fused(const float* __restrict__ b_conv, int M)
{
    extern __shared__ char smem[];
    uint32_t sbase = smem_to_u32(smem);
    const int tid = threadIdx.x, lane = tid & 31, wid = tid >> 5;
    const int warp_m = wid & 3, warp_n = wid >> 2;
    const int block_row = blockIdx.x * 128;

    #pragma unroll
    for (int i = 0; i < 8; i++) {
        int idx = tid + i * 256;
        int row = idx >> 4, cg = idx & 15;
        size_t so = (size_t)(block_row + row) * H + cg * 8;
        uint32_t off = (row * 136 + cg * 8) * 2;
        *reinterpret_cast<uint4*>(smem + FA_H_OFF + off) = *reinterpret_cast<const uint4*>(g_xh + so);
        *reinterpret_cast<uint4*>(smem + FA_L_OFF + off) = *reinterpret_cast<const uint4*>(g_xl + so);
    }
    uint4 rbh[2], rbl[2];
    fetch_b(g_wl_h, g_wl_l, 0, rbh, rbl);
    store_b_fused(smem, 0, rbh, rbl);
    __syncthreads();

    float acc[2][8][4];
    #pragma unroll
    for (int a = 0; a < 2; a++)
        #pragma unroll
        for (int b = 0; b < 8; b++)
            #pragma unroll
            for (int c = 0; c < 4; c++) acc[a][b][c] = 0.f;

    const int g = lane >> 2, t = lane & 3;

    #pragma unroll 1
    for (int q = 0; q < 12; q++) {
        int which = q >> 2, it = q & 3;
        if (q + 1 < 12) {
            int wn = (q + 1) >> 2, itn = (q + 1) & 3;
            fetch_b(g_wl_h + (size_t)wn * H * H, g_wl_l + (size_t)wn * H * H, itn * 32, rbh, rbl);
        }
        compute_tile_fused(sbase, q & 1, it * 32, warp_m, warp_n, lane, acc);
        if (q + 1 < 12)
            store_b_fused(smem, (q + 1) & 1, rbh, rbl);

        if (it == 3) {
            float* dst = (which < 2) ? (g_y + (size_t)which * NMAX * H) : g_root;
            const bool add_bias = (which == 2);
            #pragma unroll
            for (int mi = 0; mi < 2; mi++) {
                #pragma unroll
                for (int ni = 0; ni < 8; ni++) {
                    int col = warp_n * 64 + ni * 8 + t * 2;
                    float b0 = add_bias ? __ldg(&b_conv[col]) : 0.f;
                    float b1 = add_bias ? __ldg(&b_conv[col + 1]) : 0.f;
                    #pragma unroll
                    for (int half = 0; half < 2; half++) {
                        int row = block_row + warp_m * 32 + mi * 16 + g + half * 8;
                        if (row >= M) continue;
                        float v0 = acc[mi][ni][half * 2 + 0] + b0;
                        float v1 = acc[mi][ni][half * 2 + 1] + b1;
                        *reinterpret_cast<float2*>(dst + (size_t)row * H + col) = make_float2(v0, v1);
                    }
                }
            }
            #pragma unroll
            for (int a = 0; a < 2; a++)
                #pragma unroll
                for (int b = 0; b < 8; b++)
                    #pragma unroll
                    for (int c = 0; c < 4; c++) acc[a][b][c] = 0.f;
        }
        __syncthreads();
    }
}

// ---------------------- fused CSR aggregate + mean + root --------------------
// One warp per node (R5 gather loop). last==1 fuses the final GEMV.
__global__ __launch_bounds__(256) void agg_combine_kernel(
    int M, int last,
    const float* __restrict__ w_out, const float* __restrict__ b_out,
    float* __restrict__ out)
{
    int warp = (int)(((size_t)blockIdx.x * blockDim.x + threadIdx.x) >> 5);
    int lane = threadIdx.x & 31;
    if (warp >= M) return;

    size_t ridx = (size_t)warp * (H / 4) + lane;
    float4 o = reinterpret_cast<const float4*>(g_root)[ridx];

    #pragma unroll
    for (int t = 0; t < 2; t++) {
        int beg = g_off[t * NMAX + warp];
        int end = g_off[t * NMAX + warp + 1];
        int deg = end - beg;
        if (deg <= 0) continue;
        if (deg > EMAX) deg = EMAX;
        end = beg + deg;
        const float* yb = g_y + (size_t)t * NMAX * H;
        float4 s = make_float4(0.f, 0.f, 0.f, 0.f);
        for (int base = beg; base < end; base += 32) {
            int n = min(32, end - base);
            int idx = 0;
            if (lane < n) idx = g_esrc[base + lane];
            int j = 0;
            for (; j + 4 <= n; j += 4) {
                int s0 = __shfl_sync(0xFFFFFFFFu, idx, j);
                int s1 = __shfl_sync(0xFFFFFFFFu, idx, j + 1);
                int s2 = __shfl_sync(0xFFFFFFFFu, idx, j + 2);
                int s3 = __shfl_sync(0xFFFFFFFFu, idx, j + 3);
                float4 v0 = reinterpret_cast<const float4*>(yb + (size_t)s0 * H)[lane];
                float4 v1 = reinterpret_cast<const float4*>(yb + (size_t)s1 * H)[lane];
                float4 v2 = reinterpret_cast<const float4*>(yb + (size_t)s2 * H)[lane];
                float4 v3 = reinterpret_cast<const float4*>(yb + (size_t)s3 * H)[lane];
                s.x += v0.x + v1.x + v2.x + v3.x;
                s.y += v0.y + v1.y + v2.y + v3.y;
                s.z += v0.z + v1.z + v2.z + v3.z;
                s.w += v0.w + v1.w + v2.w + v3.w;
            }
            for (; j < n; j++) {
                int sj = __shfl_sync(0xFFFFFFFFu, idx, j);
                float4 v = reinterpret_cast<const float4*>(yb + (size_t)sj * H)[lane];
                s.x += v.x; s.y += v.y; s.z += v.z; s.w += v.w;
            }
        }
        float inv = 1.f / (float)deg;
        o.x += s.x * inv;
        o.y += s.y * inv;
        o.z += s.z * inv;
        o.w += s.w * inv;
    }

    if (!last) {
        uint32_t h0, l0, h1, l1;
        split2(o.x, o.y, h0, l0);
        split2(o.z, o.w, h1, l1);
        reinterpret_cast<uint2*>(g_xh)[ridx] = make_uint2(h0, h1);
        reinterpret_cast<uint2*>(g_xl)[ridx] = make_uint2(l0, l1);
    } else {
        float s0 = 0.f, s1 = 0.f, s2 = 0.f;
        int r = lane * 4;
        float xc[4] = {o.x, o.y, o.z, o.w};
        #pragma unroll
        for (int c = 0; c < 4; c++) {
            s0 = fmaf(xc[c], __ldg(&w_out[(r + c) * 3 + 0]), s0);
            s1 = fmaf(xc[c], __ldg(&w_out[(r + c) * 3 + 1]), s1);
            s2 = fmaf(xc[c], __ldg(&w_out[(r + c) * 3 + 2]), s2);
        }
        #pragma unroll
        for (int off = 16; off > 0; off >>= 1) {
            s0 += __shfl_xor_sync(0xFFFFFFFFu, s0, off);
            s1 += __shfl_xor_sync(0xFFFFFFFFu, s1, off);
            s2 += __shfl_xor_sync(0xFFFFFFFFu, s2, off);
        }
        if (lane == 0) {
            out[(size_t)warp * 3 + 0] = s0 + b_out[0];
            out[(size_t)warp * 3 + 1] = s1 + b_out[1];
            out[(size_t)warp * 3 + 2] = s2 + b_out[2];
        }
    }
}

// ------------------------------ launch glue -----------------------------------
extern "C" void kernel_launch(void* const* d_in, const int* in_sizes, int n_in,
                              void* d_out, int out_size) {
    const float* feature = (const float*)d_in[0];
    const void*  edge_index = d_in[1];
    const void*  edge_type  = d_in[2];
    const float* w_in   = (const float*)d_in[3];
    const float* b_in   = (const float*)d_in[4];
    const float* w_rel  = (const float*)d_in[5];
    const float* w_root = (const float*)d_in[6];
    const float* b_conv = (const float*)d_in[7];
    const float* w_out  = (const float*)d_in[8];
    const float* b_out  = (const float*)d_in[9];

    const int M = in_sizes[0] / DIN;      // 50000
    const int E = in_sizes[2];            // 600000
    const int tiles64  = (M + 63) / 64;   // 782
    const int tiles128 = (M + 127) / 128; // 391

    static cudaStream_t s2 = nullptr;
    static cudaEvent_t ev0 = nullptr, ev1 = nullptr;
    static bool attr_done = false;
    if (!attr_done) {
        cudaFuncSetAttribute(gemm_in_mma, cudaFuncAttributeMaxDynamicSharedMemorySize, I64_SMEM);
        cudaFuncSetAttribute(gemm_layer_fused, cudaFuncAttributeMaxDynamicSharedMemorySize, FUSED_SMEM);
        cudaStreamCreateWithFlags(&s2, cudaStreamNonBlocking);
        cudaEventCreateWithFlags(&ev0, cudaEventDisableTiming);
        cudaEventCreateWithFlags(&ev1, cudaEventDisableTiming);
        attr_done = true;
    }

    // Fork side stream for the CSR build (independent of GEMM chain)
    cudaEventRecord(ev0, 0);
    cudaStreamWaitEvent(s2, ev0, 0);

    // main chain: merged weight prep + input GEMM
    prep_weights_kernel<<<(DIN * H + 3 * H * H + 255) / 256, 256>>>(w_in, w_rel, w_root);
    zero_deg_detect_kernel<<<(KBKT + 255) / 256, 256, 0, s2>>>(edge_index, E);
    gemm_in_mma<<<tiles64, 256, I64_SMEM>>>(feature, b_in, M);

    // CSR build on side stream
    hist_kernel<<<(E + 255) / 256, 256, 0, s2>>>(edge_index, edge_type, E);
    scan1_kernel<<<NBLK, 1024, 0, s2>>>();
    scan2_kernel<<<1, 32, 0, s2>>>();
    scan3_kernel<<<NBLK, 1024, 0, s2>>>();
    fill_kernel<<<(E + 255) / 256, 256, 0, s2>>>(edge_index, edge_type, E);
    cudaEventRecord(ev1, s2);

    // layer 1 GEMM overlaps CSR tail; agg joins both chains
    gemm_layer_fused<<<tiles128, 256, FUSED_SMEM>>>(b_conv, M);
    cudaStreamWaitEvent(0, ev1, 0);
    agg_combine_kernel<<<(int)(((size_t)M * 32 + 255) / 256), 256>>>(
        M, 0, w_out, b_out, (float*)d_out);
    gemm_layer_fused<<<tiles128, 256, FUSED_SMEM>>>(b_conv, M);
    agg_combine_kernel<<<(int)(((size_t)M * 32 + 255) / 256), 256>>>(
        M, 1, w_out, b_out, (float*)d_out);
}

// round 15
// speedup vs baseline: 1.1713x; 1.0501x over previous
#include <cuda_runtime.h>
#include <cuda_bf16.h>
#include <cuda_fp16.h>
#include <cstdint>

// ---------------------------------------------------------------------------
// RGCN forward (R14 structure; gemm_in switched to fp16 2-product split):
//   h = leaky_relu(feature @ w_in + b_in)   gemm_in: fp16 split AhBh+AlBh
//   CSR build on side stream
//   per layer: z = x @ [W_r0|W_r1|W_root]   bf16 3-product fused mma kernel
//              x' = root + sum_t mean(y_t[src]) warp gather
//   layer 2 agg fuses final GEMV.
// ---------------------------------------------------------------------------

#define NMAX 50176
#define DIN  768
#define H    128
#define LEAKY_SLOPE 0.01f
#define KBKT (2 * NMAX)
#define NBLK (KBKT / 1024)
#define EMAX (1 << 20)

// ------------------------------ device scratch ------------------------------
__device__ __align__(16) float g_y[(size_t)2 * NMAX * H];
__device__ __align__(16) float g_root[(size_t)NMAX * H];
__device__ int g_idx32;

__device__ __align__(16) __nv_bfloat16 g_xh[(size_t)NMAX * H];
__device__ __align__(16) __nv_bfloat16 g_xl[(size_t)NMAX * H];
__device__ __align__(16) __half g_win_hf[(size_t)DIN * H];         // fp16 w_in (hi)
__device__ __align__(16) __nv_bfloat16 g_wl_h[(size_t)3 * H * H];  // [which][k][n]
__device__ __align__(16) __nv_bfloat16 g_wl_l[(size_t)3 * H * H];

// CSR
__device__ int g_deg[KBKT];
__device__ int g_scan[KBKT];
__device__ int g_bsum[NBLK];
__device__ int g_off[KBKT + 1];
__device__ int g_cur[KBKT];
__device__ int g_esrc[EMAX];

// ------------------------------- helpers ------------------------------------
__device__ __forceinline__ uint32_t smem_to_u32(const void* p) {
    uint32_t a;
    asm("{ .reg .u64 t; cvta.to.shared.u64 t, %1; cvt.u32.u64 %0, t; }" : "=r"(a) : "l"(p));
    return a;
}
__device__ __forceinline__ void split2(float a, float b, uint32_t& h, uint32_t& l) {
    __nv_bfloat16 ha = __float2bfloat16(a), hb = __float2bfloat16(b);
    __nv_bfloat16 la = __float2bfloat16(a - __bfloat162float(ha));
    __nv_bfloat16 lb = __float2bfloat16(b - __bfloat162float(hb));
    __nv_bfloat162 hp = __halves2bfloat162(ha, hb);
    __nv_bfloat162 lp = __halves2bfloat162(la, lb);
    h = *reinterpret_cast<uint32_t*>(&hp);
    l = *reinterpret_cast<uint32_t*>(&lp);
}
__device__ __forceinline__ void split2_f16(float a, float b, uint32_t& h, uint32_t& l) {
    __half ha = __float2half(a), hb = __float2half(b);
    __half la = __float2half(a - __half2float(ha));
    __half lb = __float2half(b - __half2float(hb));
    __half2 hp = __halves2half2(ha, hb);
    __half2 lp = __halves2half2(la, lb);
    h = *reinterpret_cast<uint32_t*>(&hp);
    l = *reinterpret_cast<uint32_t*>(&lp);
}
__device__ __forceinline__ void ldsm_x4(uint32_t (&r)[4], uint32_t addr) {
    asm volatile("ldmatrix.sync.aligned.m8n8.x4.shared.b16 {%0,%1,%2,%3}, [%4];"
                 : "=r"(r[0]), "=r"(r[1]), "=r"(r[2]), "=r"(r[3]) : "r"(addr));
}
__device__ __forceinline__ void ldsm_x4t(uint32_t& r0, uint32_t& r1, uint32_t& r2, uint32_t& r3, uint32_t addr) {
    asm volatile("ldmatrix.sync.aligned.m8n8.x4.trans.shared.b16 {%0,%1,%2,%3}, [%4];"
                 : "=r"(r0), "=r"(r1), "=r"(r2), "=r"(r3) : "r"(addr));
}
__device__ __forceinline__ void mma_bf16(float (&d)[4], const uint32_t (&a)[4], const uint32_t (&b)[2]) {
    asm volatile(
        "mma.sync.aligned.m16n8k16.row.col.f32.bf16.bf16.f32 "
        "{%0,%1,%2,%3}, {%4,%5,%6,%7}, {%8,%9}, {%0,%1,%2,%3};"
        : "+f"(d[0]), "+f"(d[1]), "+f"(d[2]), "+f"(d[3])
        : "r"(a[0]), "r"(a[1]), "r"(a[2]), "r"(a[3]), "r"(b[0]), "r"(b[1]));
}
__device__ __forceinline__ void mma_f16(float (&d)[4], const uint32_t (&a)[4], const uint32_t (&b)[2]) {
    asm volatile(
        "mma.sync.aligned.m16n8k16.row.col.f32.f16.f16.f32 "
        "{%0,%1,%2,%3}, {%4,%5,%6,%7}, {%8,%9}, {%0,%1,%2,%3};"
        : "+f"(d[0]), "+f"(d[1]), "+f"(d[2]), "+f"(d[3])
        : "r"(a[0]), "r"(a[1]), "r"(a[2]), "r"(a[3]), "r"(b[0]), "r"(b[1]));
}

// ---------------- smem layout: gemm_in 64-row tiles (fp16, no B-lo) ----------
#define I64_AH   0
#define I64_AL   10240
#define I64_BH   20480
#define I64_ABUF 5120
#define I64_BBUF 8704
#define I64_SMEM 37888

// ---------------------- smem layout: fused layer GEMM ------------------------
#define FA_H_OFF 0
#define FA_L_OFF 34816
#define FB_OFF   69632
#define FB_BUF   17408
#define FUSED_SMEM 104448

// --------------------------- index dtype handling ---------------------------
__device__ __forceinline__ int ld_idx(const void* p, long long i) {
    if (g_idx32) return ((const int*)p)[i];
    return (int)((const long long*)p)[i];
}

// -------------------- CSR build (detect fused into zero) --------------------
__global__ void zero_deg_detect_kernel(const void* ei, int E) {
    int i = blockIdx.x * blockDim.x + threadIdx.x;
    if (i < KBKT) g_deg[i] = 0;
    if (i == 0) {
        const long long* p = (const long long*)ei;
        int n = E < 256 ? E : 256;
        int is32 = 0;
        for (int k = 0; k < n; k++) {
            long long v = p[k];
            if (v < 0 || v >= (long long)NMAX) { is32 = 1; break; }
        }
        g_idx32 = is32;
    }
}
__global__ void hist_kernel(const void* ei, const void* et, int E) {
    int e = blockIdx.x * blockDim.x + threadIdx.x;
    if (e >= E) return;
    int t   = ld_idx(et, e);
    int dst = ld_idx(ei, (long long)E + e);
    atomicAdd(&g_deg[t * NMAX + dst], 1);
}
__global__ __launch_bounds__(1024) void scan1_kernel() {
    int i = blockIdx.x * 1024 + threadIdx.x;
    int lane = threadIdx.x & 31, w = threadIdx.x >> 5;
    int x = g_deg[i];
    #pragma unroll
    for (int off = 1; off < 32; off <<= 1) {
        int y = __shfl_up_sync(0xFFFFFFFFu, x, off);
        if (lane >= off) x += y;
    }
    __shared__ int wsum[32];
    if (lane == 31) wsum[w] = x;
    __syncthreads();
    if (w == 0) {
        int s = wsum[lane];
        #pragma unroll
        for (int off = 1; off < 32; off <<= 1) {
            int y = __shfl_up_sync(0xFFFFFFFFu, s, off);
            if (lane >= off) s += y;
        }
        wsum[lane] = s;
    }
    __syncthreads();
    if (w > 0) x += wsum[w - 1];
    g_scan[i] = x;
    if (threadIdx.x == 1023) g_bsum[blockIdx.x] = x;
}
__global__ __launch_bounds__(32) void scan2_kernel() {
    int lane = threadIdx.x;
    int carry = 0;
    for (int base = 0; base < NBLK; base += 32) {
        int i = base + lane;
        int x = (i < NBLK) ? g_bsum[i] : 0;
        #pragma unroll
        for (int off = 1; off < 32; off <<= 1) {
            int y = __shfl_up_sync(0xFFFFFFFFu, x, off);
            if (lane >= off) x += y;
        }
        x += carry;
        if (i < NBLK) g_bsum[i] = x;
        carry = __shfl_sync(0xFFFFFFFFu, x, 31);
    }
}
__global__ __launch_bounds__(1024) void scan3_kernel() {
    int i = blockIdx.x * 1024 + threadIdx.x;
    int blk = blockIdx.x;
    int off = g_scan[i] - g_deg[i] + (blk > 0 ? g_bsum[blk - 1] : 0);
    g_off[i] = off;
    g_cur[i] = off;
    if (i == KBKT - 1) g_off[KBKT] = g_bsum[NBLK - 1];
}
__global__ void fill_kernel(const void* ei, const void* et, int E) {
    int e = blockIdx.x * blockDim.x + threadIdx.x;
    if (e >= E) return;
    int src = ld_idx(ei, e);
    int dst = ld_idx(ei, (long long)E + e);
    int t   = ld_idx(et, e);
    int pos = atomicAdd(&g_cur[t * NMAX + dst], 1);
    if (pos >= 0 && pos < EMAX) g_esrc[pos] = src;
}

// ---------------- weight prep, single merged kernel --------------------------
__global__ void prep_weights_kernel(const float* __restrict__ w_in,
                                    const float* __restrict__ w_rel,
                                    const float* __restrict__ w_root) {
    int idx = blockIdx.x * blockDim.x + threadIdx.x;
    const int NIN = DIN * H;           // 98304
    const int NL  = 3 * H * H;         // 49152
    if (idx < NIN) {
        g_win_hf[idx] = __float2half(w_in[idx]);
    } else if (idx < NIN + NL) {
        int j = idx - NIN;
        float v = (j < 2 * H * H) ? w_rel[j] : w_root[j - 2 * H * H];
        __nv_bfloat16 h = __float2bfloat16(v);
        g_wl_h[j] = h;
        g_wl_l[j] = __float2bfloat16(v - __bfloat162float(h));
    }
}

// ------------------------------ tile fetch/store -----------------------------
__device__ __forceinline__ void fetch_a_f32_64(const float* __restrict__ A, int block_row, int M,
                                               int k0, float4 (&r)[2]) {
    int tid = threadIdx.x;
    #pragma unroll
    for (int i = 0; i < 2; i++) {
        int idx = tid + i * 256;
        int row = idx >> 3, c4 = idx & 7;
        int gr = block_row + row; if (gr >= M) gr = M - 1;
        r[i] = *reinterpret_cast<const float4*>(A + (size_t)gr * DIN + k0 + c4 * 4);
    }
}
__device__ __forceinline__ void store_a_split_64(char* smem, int buf, const float4 (&r)[2]) {
    int tid = threadIdx.x;
    #pragma unroll
    for (int i = 0; i < 2; i++) {
        int idx = tid + i * 256;
        int row = idx >> 3, c4 = idx & 7;
        uint32_t h0, l0, h1, l1;
        split2_f16(r[i].x, r[i].y, h0, l0);
        split2_f16(r[i].z, r[i].w, h1, l1);
        uint32_t off = (row * 40 + c4 * 4) * 2;
        *reinterpret_cast<uint2*>(smem + I64_AH + buf * I64_ABUF + off) = make_uint2(h0, h1);
        *reinterpret_cast<uint2*>(smem + I64_AL + buf * I64_ABUF + off) = make_uint2(l0, l1);
    }
}
// bf16 dual-array fetch (layer weights)
__device__ __forceinline__ void fetch_b(const __nv_bfloat16* __restrict__ bh,
                                        const __nv_bfloat16* __restrict__ bl,
                                        int k0, uint4 (&rh)[2], uint4 (&rl)[2]) {
    int tid = threadIdx.x;
    #pragma unroll
    for (int i = 0; i < 2; i++) {
        int idx = tid + i * 256;
        int row = idx >> 4, col = (idx & 15) * 8;
        size_t so = (size_t)(k0 + row) * H + col;
        rh[i] = *reinterpret_cast<const uint4*>(bh + so);
        rl[i] = *reinterpret_cast<const uint4*>(bl + so);
    }
}
// fp16 hi-only fetch (input weights)
__device__ __forceinline__ void fetch_b_h(int k0, uint4 (&rh)[2]) {
    int tid = threadIdx.x;
    #pragma unroll
    for (int i = 0; i < 2; i++) {
        int idx = tid + i * 256;
        int row = idx >> 4, col = (idx & 15) * 8;
        size_t so = (size_t)(k0 + row) * H + col;
        rh[i] = *reinterpret_cast<const uint4*>(g_win_hf + so);
    }
}
__device__ __forceinline__ void store_b_64h(char* smem, int buf, const uint4 (&rh)[2]) {
    int tid = threadIdx.x;
    #pragma unroll
    for (int i = 0; i < 2; i++) {
        int idx = tid + i * 256;
        int row = idx >> 4, col = (idx & 15) * 8;
        uint32_t off = (row * 136 + col) * 2;
        *reinterpret_cast<uint4*>(smem + I64_BH + buf * I64_BBUF + off) = rh[i];
    }
}
__device__ __forceinline__ void store_b_fused(char* smem, int buf, const uint4 (&rh)[2], const uint4 (&rl)[2]) {
    int tid = threadIdx.x;
    #pragma unroll
    for (int i = 0; i < 2; i++) {
        int idx = tid + i * 256;
        int row = idx >> 4, col = (idx & 15) * 8;
        uint32_t off = (row * 136 + col) * 2;
        *reinterpret_cast<uint4*>(smem + FB_OFF + buf * FB_BUF + off) = rh[i];
        *reinterpret_cast<uint4*>(smem + FB_OFF + buf * FB_BUF + 8704 + off) = rl[i];
    }
}

// ------------------------------- compute cores --------------------------------
// gemm_in: fp16 2-product (AhBh + AlBh), B hi only
__device__ __forceinline__ void compute_tile_64(uint32_t sbase, int buf, int warp_m, int warp_n,
                                                int lane, float (&acc)[2][4][4]) {
    uint32_t abase_h = sbase + I64_AH + buf * I64_ABUF;
    uint32_t abase_l = sbase + I64_AL + buf * I64_ABUF;
    uint32_t bbase_h = sbase + I64_BH + buf * I64_BBUF;
    #pragma unroll
    for (int ks = 0; ks < 2; ks++) {
        uint32_t ah[2][4], al[2][4];
        #pragma unroll
        for (int mi = 0; mi < 2; mi++) {
            int m0 = warp_m * 32 + mi * 16;
            uint32_t aoff = ((m0 + (lane & 15)) * 40 + ks * 16 + ((lane >> 4) << 3)) * 2;
            ldsm_x4(ah[mi], abase_h + aoff);
            ldsm_x4(al[mi], abase_l + aoff);
        }
        uint32_t bh[4][2];
        #pragma unroll
        for (int nb = 0; nb < 2; nb++) {
            int n0 = warp_n * 32 + nb * 16;
            int krow = ks * 16 + ((lane >> 3) & 1) * 8 + (lane & 7);
            int ncol = n0 + (lane >> 4) * 8;
            uint32_t boff = (krow * 136 + ncol) * 2;
            uint32_t r0, r1, r2, r3;
            ldsm_x4t(r0, r1, r2, r3, bbase_h + boff);
            bh[nb * 2][0] = r0; bh[nb * 2][1] = r1; bh[nb * 2 + 1][0] = r2; bh[nb * 2 + 1][1] = r3;
        }
        #pragma unroll
        for (int mi = 0; mi < 2; mi++)
            #pragma unroll
            for (int ni = 0; ni < 4; ni++) {
                mma_f16(acc[mi][ni], ah[mi], bh[ni]);
                mma_f16(acc[mi][ni], al[mi], bh[ni]);
            }
    }
}

__device__ __forceinline__ void compute_tile_fused(uint32_t sbase, int bbuf, int kpos,
                                                   int warp_m, int warp_n,
                                                   int lane, float (&acc)[2][8][4]) {
    uint32_t bbase_h = sbase + FB_OFF + bbuf * FB_BUF;
    uint32_t bbase_l = bbase_h + 8704;
    #pragma unroll
    for (int ks = 0; ks < 2; ks++) {
        int kk = kpos + ks * 16;
        uint32_t ah[2][4], al[2][4];
        #pragma unroll
        for (int mi = 0; mi < 2; mi++) {
            int m0 = warp_m * 32 + mi * 16;
            uint32_t aoff = ((m0 + (lane & 15)) * 136 + kk + ((lane >> 4) << 3)) * 2;
            ldsm_x4(ah[mi], sbase + FA_H_OFF + aoff);
            ldsm_x4(al[mi], sbase + FA_L_OFF + aoff);
        }
        uint32_t bh[8][2], bl[8][2];
        #pragma unroll
        for (int nb = 0; nb < 4; nb++) {
            int n0 = warp_n * 64 + nb * 16;
            int krow = ks * 16 + ((lane >> 3) & 1) * 8 + (lane & 7);
            int ncol = n0 + (lane >> 4) * 8;
            uint32_t boff = (krow * 136 + ncol) * 2;
            uint32_t r0, r1, r2, r3;
            ldsm_x4t(r0, r1, r2, r3, bbase_h + boff);
            bh[nb * 2][0] = r0; bh[nb * 2][1] = r1; bh[nb * 2 + 1][0] = r2; bh[nb * 2 + 1][1] = r3;
            ldsm_x4t(r0, r1, r2, r3, bbase_l + boff);
            bl[nb * 2][0] = r0; bl[nb * 2][1] = r1; bl[nb * 2 + 1][0] = r2; bl[nb * 2 + 1][1] = r3;
        }
        #pragma unroll
        for (int mi = 0; mi < 2; mi++)
            #pragma unroll
            for (int ni = 0; ni < 8; ni++) {
                mma_bf16(acc[mi][ni], ah[mi], bh[ni]);
                mma_bf16(acc[mi][ni], al[mi], bh[ni]);
                mma_bf16(acc[mi][ni], ah[mi], bl[ni]);
            }
    }
}

// ------------------- GEMM 1: feature @ w_in (fp16 2-product) ------------------
__global__ __launch_bounds__(256, 2) void gemm_in_mma(
    const float* __restrict__ A, const float* __restrict__ bias, int M)
{
    extern __shared__ char smem[];
    uint32_t sbase = smem_to_u32(smem);
    const int tid = threadIdx.x, lane = tid & 31, wid = tid >> 5;
    const int warp_m = wid & 1, warp_n = wid >> 1;
    const int block_row = blockIdx.x * 64;

    float acc[2][4][4];
    #pragma unroll
    for (int a = 0; a < 2; a++)
        #pragma unroll
        for (int b = 0; b < 4; b++)
            #pragma unroll
            for (int c = 0; c < 4; c++) acc[a][b][c] = 0.f;

    float4 ra[2];
    uint4 rbh[2];
    fetch_a_f32_64(A, block_row, M, 0, ra);
    fetch_b_h(0, rbh);
    store_a_split_64(smem, 0, ra);
    store_b_64h(smem, 0, rbh);
    __syncthreads();

    const int NIT = DIN / 32;  // 24
    #pragma unroll 1
    for (int it = 0; it < NIT; it++) {
        if (it + 1 < NIT) {
            fetch_a_f32_64(A, block_row, M, (it + 1) * 32, ra);
            fetch_b_h((it + 1) * 32, rbh);
        }
        compute_tile_64(sbase, it & 1, warp_m, warp_n, lane, acc);
        if (it + 1 < NIT) {
            store_a_split_64(smem, (it + 1) & 1, ra);
            store_b_64h(smem, (it + 1) & 1, rbh);
        }
        __syncthreads();
    }

    const int g = lane >> 2, t = lane & 3;
    #pragma unroll
    for (int mi = 0; mi < 2; mi++) {
        #pragma unroll
        for (int ni = 0; ni < 4; ni++) {
            int col = warp_n * 32 + ni * 8 + t * 2;
            float b0 = __ldg(&bias[col]), b1 = __ldg(&bias[col + 1]);
            #pragma unroll
            for (int half = 0; half < 2; half++) {
                int row = block_row + warp_m * 32 + mi * 16 + g + half * 8;
                if (row >= M) continue;
                float v0 = acc[mi][ni][half * 2 + 0] + b0;
                float v1 = acc[mi][ni][half * 2 + 1] + b1;
                v0 = v0 >= 0.f ? v0 : LEAKY_SLOPE * v0;
                v1 = v1 >= 0.f ? v1 : LEAKY_SLOPE * v1;
                uint32_t h, l;
                split2(v0, v1, h, l);
                *reinterpret_cast<uint32_t*>(g_xh + (size_t)row * H + col) = h;
                *reinterpret_cast<uint32_t*>(g_xl + (size_t)row * H + col) = l;
            }
        }
    }
}

// --------------- fused layer GEMM: z = x @ {W_r0, W_r1, W_root} --------------
__global__ __launch_bounds__(256, 2) void gemm_layer_fused(const float* __restrict__ b_conv, int M)
{
    extern __shared__ char smem[];
    uint32_t sbase = smem_to_u32(smem);
    const int tid = threadIdx.x, lane = tid & 31, wid = tid >> 5;
    const int warp_m = wid & 3, warp_n = wid >> 2;
    const int block_row = blockIdx.x * 128;

    #pragma unroll
    for (int i = 0; i < 8; i++) {
        int idx = tid + i * 256;
        int row = idx >> 4, cg = idx & 15;
        size_t so = (size_t)(block_row + row) * H + cg * 8;
        uint32_t off = (row * 136 + cg * 8) * 2;
        *reinterpret_cast<uint4*>(smem + FA_H_OFF + off) = *reinterpret_cast<const uint4*>(g_xh + so);
        *reinterpret_cast<uint4*>(smem + FA_L_OFF + off) = *reinterpret_cast<const uint4*>(g_xl + so);
    }
    uint4 rbh[2], rbl[2];
    fetch_b(g_wl_h, g_wl_l, 0, rbh, rbl);
    store_b_fused(smem, 0, rbh, rbl);
    __syncthreads();

    float acc[2][8][4];
    #pragma unroll
    for (int a = 0; a < 2; a++)
        #pragma unroll
        for (int b = 0; b < 8; b++)
            #pragma unroll
            for (int c = 0; c < 4; c++) acc[a][b][c] = 0.f;

    const int g = lane >> 2, t = lane & 3;

    #pragma unroll 1
    for (int q = 0; q < 12; q++) {
        int which = q >> 2, it = q & 3;
        if (q + 1 < 12) {
            int wn = (q + 1) >> 2, itn = (q + 1) & 3;
            fetch_b(g_wl_h + (size_t)wn * H * H, g_wl_l + (size_t)wn * H * H, itn * 32, rbh, rbl);
        }
        compute_tile_fused(sbase, q & 1, it * 32, warp_m, warp_n, lane, acc);
        if (q + 1 < 12)
            store_b_fused(smem, (q + 1) & 1, rbh, rbl);

        if (it == 3) {
            float* dst = (which < 2) ? (g_y + (size_t)which * NMAX * H) : g_root;
            const bool add_bias = (which == 2);
            #pragma unroll
            for (int mi = 0; mi < 2; mi++) {
                #pragma unroll
                for (int ni = 0; ni < 8; ni++) {
                    int col = warp_n * 64 + ni * 8 + t * 2;
                    float b0 = add_bias ? __ldg(&b_conv[col]) : 0.f;
                    float b1 = add_bias ? __ldg(&b_conv[col + 1]) : 0.f;
                    #pragma unroll
                    for (int half = 0; half < 2; half++) {
                        int row = block_row + warp_m * 32 + mi * 16 + g + half * 8;
                        if (row >= M) continue;
                        float v0 = acc[mi][ni][half * 2 + 0] + b0;
                        float v1 = acc[mi][ni][half * 2 + 1] + b1;
                        *reinterpret_cast<float2*>(dst + (size_t)row * H + col) = make_float2(v0, v1);
                    }
                }
            }
            #pragma unroll
            for (int a = 0; a < 2; a++)
                #pragma unroll
                for (int b = 0; b < 8; b++)
                    #pragma unroll
                    for (int c = 0; c < 4; c++) acc[a][b][c] = 0.f;
        }
        __syncthreads();
    }
}

// ---------------------- fused CSR aggregate + mean + root --------------------
__global__ __launch_bounds__(256) void agg_combine_kernel(
    int M, int last,
    const float* __restrict__ w_out, const float* __restrict__ b_out,
    float* __restrict__ out)
{
    int warp = (int)(((size_t)blockIdx.x * blockDim.x + threadIdx.x) >> 5);
    int lane = threadIdx.x & 31;
    if (warp >= M) return;

    size_t ridx = (size_t)warp * (H / 4) + lane;
    float4 o = reinterpret_cast<const float4*>(g_root)[ridx];

    #pragma unroll
    for (int t = 0; t < 2; t++) {
        int beg = g_off[t * NMAX + warp];
        int end = g_off[t * NMAX + warp + 1];
        int deg = end - beg;
        if (deg <= 0) continue;
        if (deg > EMAX) deg = EMAX;
        end = beg + deg;
        const float* yb = g_y + (size_t)t * NMAX * H;
        float4 s = make_float4(0.f, 0.f, 0.f, 0.f);
        for (int base = beg; base < end; base += 32) {
            int n = min(32, end - base);
            int idx = 0;
            if (lane < n) idx = g_esrc[base + lane];
            int j = 0;
            for (; j + 4 <= n; j += 4) {
                int s0 = __shfl_sync(0xFFFFFFFFu, idx, j);
                int s1 = __shfl_sync(0xFFFFFFFFu, idx, j + 1);
                int s2 = __shfl_sync(0xFFFFFFFFu, idx, j + 2);
                int s3 = __shfl_sync(0xFFFFFFFFu, idx, j + 3);
                float4 v0 = reinterpret_cast<const float4*>(yb + (size_t)s0 * H)[lane];
                float4 v1 = reinterpret_cast<const float4*>(yb + (size_t)s1 * H)[lane];
                float4 v2 = reinterpret_cast<const float4*>(yb + (size_t)s2 * H)[lane];
                float4 v3 = reinterpret_cast<const float4*>(yb + (size_t)s3 * H)[lane];
                s.x += v0.x + v1.x + v2.x + v3.x;
                s.y += v0.y + v1.y + v2.y + v3.y;
                s.z += v0.z + v1.z + v2.z + v3.z;
                s.w += v0.w + v1.w + v2.w + v3.w;
            }
            for (; j < n; j++) {
                int sj = __shfl_sync(0xFFFFFFFFu, idx, j);
                float4 v = reinterpret_cast<const float4*>(yb + (size_t)sj * H)[lane];
                s.x += v.x; s.y += v.y; s.z += v.z; s.w += v.w;
            }
        }
        float inv = 1.f / (float)deg;
        o.x += s.x * inv;
        o.y += s.y * inv;
        o.z += s.z * inv;
        o.w += s.w * inv;
    }

    if (!last) {
        uint32_t h0, l0, h1, l1;
        split2(o.x, o.y, h0, l0);
        split2(o.z, o.w, h1, l1);
        reinterpret_cast<uint2*>(g_xh)[ridx] = make_uint2(h0, h1);
        reinterpret_cast<uint2*>(g_xl)[ridx] = make_uint2(l0, l1);
    } else {
        float s0 = 0.f, s1 = 0.f, s2 = 0.f;
        int r = lane * 4;
        float xc[4] = {o.x, o.y, o.z, o.w};
        #pragma unroll
        for (int c = 0; c < 4; c++) {
            s0 = fmaf(xc[c], __ldg(&w_out[(r + c) * 3 + 0]), s0);
            s1 = fmaf(xc[c], __ldg(&w_out[(r + c) * 3 + 1]), s1);
            s2 = fmaf(xc[c], __ldg(&w_out[(r + c) * 3 + 2]), s2);
        }
        #pragma unroll
        for (int off = 16; off > 0; off >>= 1) {
            s0 += __shfl_xor_sync(0xFFFFFFFFu, s0, off);
            s1 += __shfl_xor_sync(0xFFFFFFFFu, s1, off);
            s2 += __shfl_xor_sync(0xFFFFFFFFu, s2, off);
        }
        if (lane == 0) {
            out[(size_t)warp * 3 + 0] = s0 + b_out[0];
            out[(size_t)warp * 3 + 1] = s1 + b_out[1];
            out[(size_t)warp * 3 + 2] = s2 + b_out[2];
        }
    }
}

// ------------------------------ launch glue -----------------------------------
extern "C" void kernel_launch(void* const* d_in, const int* in_sizes, int n_in,
                              void* d_out, int out_size) {
    const float* feature = (const float*)d_in[0];
    const void*  edge_index = d_in[1];
    const void*  edge_type  = d_in[2];
    const float* w_in   = (const float*)d_in[3];
    const float* b_in   = (const float*)d_in[4];
    const float* w_rel  = (const float*)d_in[5];
    const float* w_root = (const float*)d_in[6];
    const float* b_conv = (const float*)d_in[7];
    const float* w_out  = (const float*)d_in[8];
    const float* b_out  = (const float*)d_in[9];

    const int M = in_sizes[0] / DIN;      // 50000
    const int E = in_sizes[2];            // 600000
    const int tiles64  = (M + 63) / 64;   // 782
    const int tiles128 = (M + 127) / 128; // 391

    static cudaStream_t s2 = nullptr;
    static cudaEvent_t ev0 = nullptr, ev1 = nullptr;
    static bool attr_done = false;
    if (!attr_done) {
        cudaFuncSetAttribute(gemm_in_mma, cudaFuncAttributeMaxDynamicSharedMemorySize, I64_SMEM);
        cudaFuncSetAttribute(gemm_layer_fused, cudaFuncAttributeMaxDynamicSharedMemorySize, FUSED_SMEM);
        cudaStreamCreateWithFlags(&s2, cudaStreamNonBlocking);
        cudaEventCreateWithFlags(&ev0, cudaEventDisableTiming);
        cudaEventCreateWithFlags(&ev1, cudaEventDisableTiming);
        attr_done = true;
    }

    // Fork side stream for the CSR build (independent of GEMM chain)
    cudaEventRecord(ev0, 0);
    cudaStreamWaitEvent(s2, ev0, 0);

    // main chain: merged weight prep + input GEMM
    prep_weights_kernel<<<(DIN * H + 3 * H * H + 255) / 256, 256>>>(w_in, w_rel, w_root);
    zero_deg_detect_kernel<<<(KBKT + 255) / 256, 256, 0, s2>>>(edge_index, E);
    gemm_in_mma<<<tiles64, 256, I64_SMEM>>>(feature, b_in, M);

    // CSR build on side stream
    hist_kernel<<<(E + 255) / 256, 256, 0, s2>>>(edge_index, edge_type, E);
    scan1_kernel<<<NBLK, 1024, 0, s2>>>();
    scan2_kernel<<<1, 32, 0, s2>>>();
    scan3_kernel<<<NBLK, 1024, 0, s2>>>();
    fill_kernel<<<(E + 255) / 256, 256, 0, s2>>>(edge_index, edge_type, E);
    cudaEventRecord(ev1, s2);

    // layer 1 GEMM overlaps CSR tail; agg joins both chains
    gemm_layer_fused<<<tiles128, 256, FUSED_SMEM>>>(b_conv, M);
    cudaStreamWaitEvent(0, ev1, 0);
    agg_combine_kernel<<<(int)(((size_t)M * 32 + 255) / 256), 256>>>(
        M, 0, w_out, b_out, (float*)d_out);
    gemm_layer_fused<<<tiles128, 256, FUSED_SMEM>>>(b_conv, M);
    agg_combine_kernel<<<(int)(((size_t)M * 32 + 255) / 256), 256>>>(
        M, 1, w_out, b_out, (float*)d_out);
}

// round 16
// speedup vs baseline: 1.3050x; 1.1141x over previous
#include <cuda_runtime.h>
#include <cuda_bf16.h>
#include <cuda_fp16.h>
#include <cstdint>

// ---------------------------------------------------------------------------
// RGCN forward — all GEMMs fp16 2-product split (Ah*Bh + Al*Bh, fp32 accum):
//   h = leaky_relu(feature @ w_in + b_in)   gemm_in (64-row tiles)
//   CSR build on side stream
//   per layer: z = x @ [W_r0|W_r1|W_root]   fused layer GEMM (fp16 2-product)
//              x' = root + sum_t mean(y_t[src]) warp gather
//   layer 2 agg fuses final GEMV.
// ---------------------------------------------------------------------------

#define NMAX 50176
#define DIN  768
#define H    128
#define LEAKY_SLOPE 0.01f
#define KBKT (2 * NMAX)
#define NBLK (KBKT / 1024)
#define EMAX (1 << 20)

// ------------------------------ device scratch ------------------------------
__device__ __align__(16) float g_y[(size_t)2 * NMAX * H];
__device__ __align__(16) float g_root[(size_t)NMAX * H];
__device__ int g_idx32;

__device__ __align__(16) __half g_xh[(size_t)NMAX * H];           // x hi (fp16)
__device__ __align__(16) __half g_xl[(size_t)NMAX * H];           // x lo (fp16)
__device__ __align__(16) __half g_win_hf[(size_t)DIN * H];        // w_in (fp16 hi)
__device__ __align__(16) __half g_wl_hf[(size_t)3 * H * H];       // layer W (fp16 hi)

// CSR
__device__ int g_deg[KBKT];
__device__ int g_scan[KBKT];
__device__ int g_bsum[NBLK];
__device__ int g_off[KBKT + 1];
__device__ int g_cur[KBKT];
__device__ int g_esrc[EMAX];

// ------------------------------- helpers ------------------------------------
__device__ __forceinline__ uint32_t smem_to_u32(const void* p) {
    uint32_t a;
    asm("{ .reg .u64 t; cvta.to.shared.u64 t, %1; cvt.u32.u64 %0, t; }" : "=r"(a) : "l"(p));
    return a;
}
__device__ __forceinline__ void split2_f16(float a, float b, uint32_t& h, uint32_t& l) {
    __half ha = __float2half(a), hb = __float2half(b);
    __half la = __float2half(a - __half2float(ha));
    __half lb = __float2half(b - __half2float(hb));
    __half2 hp = __halves2half2(ha, hb);
    __half2 lp = __halves2half2(la, lb);
    h = *reinterpret_cast<uint32_t*>(&hp);
    l = *reinterpret_cast<uint32_t*>(&lp);
}
__device__ __forceinline__ void ldsm_x4(uint32_t (&r)[4], uint32_t addr) {
    asm volatile("ldmatrix.sync.aligned.m8n8.x4.shared.b16 {%0,%1,%2,%3}, [%4];"
                 : "=r"(r[0]), "=r"(r[1]), "=r"(r[2]), "=r"(r[3]) : "r"(addr));
}
__device__ __forceinline__ void ldsm_x4t(uint32_t& r0, uint32_t& r1, uint32_t& r2, uint32_t& r3, uint32_t addr) {
    asm volatile("ldmatrix.sync.aligned.m8n8.x4.trans.shared.b16 {%0,%1,%2,%3}, [%4];"
                 : "=r"(r0), "=r"(r1), "=r"(r2), "=r"(r3) : "r"(addr));
}
__device__ __forceinline__ void mma_f16(float (&d)[4], const uint32_t (&a)[4], const uint32_t (&b)[2]) {
    asm volatile(
        "mma.sync.aligned.m16n8k16.row.col.f32.f16.f16.f32 "
        "{%0,%1,%2,%3}, {%4,%5,%6,%7}, {%8,%9}, {%0,%1,%2,%3};"
        : "+f"(d[0]), "+f"(d[1]), "+f"(d[2]), "+f"(d[3])
        : "r"(a[0]), "r"(a[1]), "r"(a[2]), "r"(a[3]), "r"(b[0]), "r"(b[1]));
}

// ---------------- smem layout: gemm_in 64-row tiles (fp16, no B-lo) ----------
#define I64_AH   0
#define I64_AL   10240
#define I64_BH   20480
#define I64_ABUF 5120
#define I64_BBUF 8704
#define I64_SMEM 37888

// ---------------- smem layout: fused layer GEMM (fp16, B hi only) ------------
#define FA_H_OFF 0
#define FA_L_OFF 34816
#define FB_OFF   69632
#define FB_BUF   8704
#define FUSED_SMEM 87040

// --------------------------- index dtype handling ---------------------------
__device__ __forceinline__ int ld_idx(const void* p, long long i) {
    if (g_idx32) return ((const int*)p)[i];
    return (int)((const long long*)p)[i];
}

// -------------------- CSR build (detect fused into zero) --------------------
__global__ void zero_deg_detect_kernel(const void* ei, int E) {
    int i = blockIdx.x * blockDim.x + threadIdx.x;
    if (i < KBKT) g_deg[i] = 0;
    if (i == 0) {
        const long long* p = (const long long*)ei;
        int n = E < 256 ? E : 256;
        int is32 = 0;
        for (int k = 0; k < n; k++) {
            long long v = p[k];
            if (v < 0 || v >= (long long)NMAX) { is32 = 1; break; }
        }
        g_idx32 = is32;
    }
}
__global__ void hist_kernel(const void* ei, const void* et, int E) {
    int e = blockIdx.x * blockDim.x + threadIdx.x;
    if (e >= E) return;
    int t   = ld_idx(et, e);
    int dst = ld_idx(ei, (long long)E + e);
    atomicAdd(&g_deg[t * NMAX + dst], 1);
}
__global__ __launch_bounds__(1024) void scan1_kernel() {
    int i = blockIdx.x * 1024 + threadIdx.x;
    int lane = threadIdx.x & 31, w = threadIdx.x >> 5;
    int x = g_deg[i];
    #pragma unroll
    for (int off = 1; off < 32; off <<= 1) {
        int y = __shfl_up_sync(0xFFFFFFFFu, x, off);
        if (lane >= off) x += y;
    }
    __shared__ int wsum[32];
    if (lane == 31) wsum[w] = x;
    __syncthreads();
    if (w == 0) {
        int s = wsum[lane];
        #pragma unroll
        for (int off = 1; off < 32; off <<= 1) {
            int y = __shfl_up_sync(0xFFFFFFFFu, s, off);
            if (lane >= off) s += y;
        }
        wsum[lane] = s;
    }
    __syncthreads();
    if (w > 0) x += wsum[w - 1];
    g_scan[i] = x;
    if (threadIdx.x == 1023) g_bsum[blockIdx.x] = x;
}
__global__ __launch_bounds__(32) void scan2_kernel() {
    int lane = threadIdx.x;
    int carry = 0;
    for (int base = 0; base < NBLK; base += 32) {
        int i = base + lane;
        int x = (i < NBLK) ? g_bsum[i] : 0;
        #pragma unroll
        for (int off = 1; off < 32; off <<= 1) {
            int y = __shfl_up_sync(0xFFFFFFFFu, x, off);
            if (lane >= off) x += y;
        }
        x += carry;
        if (i < NBLK) g_bsum[i] = x;
        carry = __shfl_sync(0xFFFFFFFFu, x, 31);
    }
}
__global__ __launch_bounds__(1024) void scan3_kernel() {
    int i = blockIdx.x * 1024 + threadIdx.x;
    int blk = blockIdx.x;
    int off = g_scan[i] - g_deg[i] + (blk > 0 ? g_bsum[blk - 1] : 0);
    g_off[i] = off;
    g_cur[i] = off;
    if (i == KBKT - 1) g_off[KBKT] = g_bsum[NBLK - 1];
}
__global__ void fill_kernel(const void* ei, const void* et, int E) {
    int e = blockIdx.x * blockDim.x + threadIdx.x;
    if (e >= E) return;
    int src = ld_idx(ei, e);
    int dst = ld_idx(ei, (long long)E + e);
    int t   = ld_idx(et, e);
    int pos = atomicAdd(&g_cur[t * NMAX + dst], 1);
    if (pos >= 0 && pos < EMAX) g_esrc[pos] = src;
}

// ---------------- weight prep, single merged kernel --------------------------
__global__ void prep_weights_kernel(const float* __restrict__ w_in,
                                    const float* __restrict__ w_rel,
                                    const float* __restrict__ w_root) {
    int idx = blockIdx.x * blockDim.x + threadIdx.x;
    const int NIN = DIN * H;           // 98304
    const int NL  = 3 * H * H;         // 49152
    if (idx < NIN) {
        g_win_hf[idx] = __float2half(w_in[idx]);
    } else if (idx < NIN + NL) {
        int j = idx - NIN;
        float v = (j < 2 * H * H) ? w_rel[j] : w_root[j - 2 * H * H];
        g_wl_hf[j] = __float2half(v);
    }
}

// ------------------------------ tile fetch/store -----------------------------
__device__ __forceinline__ void fetch_a_f32_64(const float* __restrict__ A, int block_row, int M,
                                               int k0, float4 (&r)[2]) {
    int tid = threadIdx.x;
    #pragma unroll
    for (int i = 0; i < 2; i++) {
        int idx = tid + i * 256;
        int row = idx >> 3, c4 = idx & 7;
        int gr = block_row + row; if (gr >= M) gr = M - 1;
        r[i] = *reinterpret_cast<const float4*>(A + (size_t)gr * DIN + k0 + c4 * 4);
    }
}
__device__ __forceinline__ void store_a_split_64(char* smem, int buf, const float4 (&r)[2]) {
    int tid = threadIdx.x;
    #pragma unroll
    for (int i = 0; i < 2; i++) {
        int idx = tid + i * 256;
        int row = idx >> 3, c4 = idx & 7;
        uint32_t h0, l0, h1, l1;
        split2_f16(r[i].x, r[i].y, h0, l0);
        split2_f16(r[i].z, r[i].w, h1, l1);
        uint32_t off = (row * 40 + c4 * 4) * 2;
        *reinterpret_cast<uint2*>(smem + I64_AH + buf * I64_ABUF + off) = make_uint2(h0, h1);
        *reinterpret_cast<uint2*>(smem + I64_AL + buf * I64_ABUF + off) = make_uint2(l0, l1);
    }
}
// fp16 hi-only fetch from a weight array
__device__ __forceinline__ void fetch_b_h(const __half* __restrict__ bh, int k0, uint4 (&rh)[2]) {
    int tid = threadIdx.x;
    #pragma unroll
    for (int i = 0; i < 2; i++) {
        int idx = tid + i * 256;
        int row = idx >> 4, col = (idx & 15) * 8;
        size_t so = (size_t)(k0 + row) * H + col;
        rh[i] = *reinterpret_cast<const uint4*>(bh + so);
    }
}
__device__ __forceinline__ void store_b_64h(char* smem, int buf, const uint4 (&rh)[2]) {
    int tid = threadIdx.x;
    #pragma unroll
    for (int i = 0; i < 2; i++) {
        int idx = tid + i * 256;
        int row = idx >> 4, col = (idx & 15) * 8;
        uint32_t off = (row * 136 + col) * 2;
        *reinterpret_cast<uint4*>(smem + I64_BH + buf * I64_BBUF + off) = rh[i];
    }
}
__device__ __forceinline__ void store_b_fused(char* smem, int buf, const uint4 (&rh)[2]) {
    int tid = threadIdx.x;
    #pragma unroll
    for (int i = 0; i < 2; i++) {
        int idx = tid + i * 256;
        int row = idx >> 4, col = (idx & 15) * 8;
        uint32_t off = (row * 136 + col) * 2;
        *reinterpret_cast<uint4*>(smem + FB_OFF + buf * FB_BUF + off) = rh[i];
    }
}

// ------------------------------- compute cores --------------------------------
// gemm_in: fp16 2-product (AhBh + AlBh)
__device__ __forceinline__ void compute_tile_64(uint32_t sbase, int buf, int warp_m, int warp_n,
                                                int lane, float (&acc)[2][4][4]) {
    uint32_t abase_h = sbase + I64_AH + buf * I64_ABUF;
    uint32_t abase_l = sbase + I64_AL + buf * I64_ABUF;
    uint32_t bbase_h = sbase + I64_BH + buf * I64_BBUF;
    #pragma unroll
    for (int ks = 0; ks < 2; ks++) {
        uint32_t ah[2][4], al[2][4];
        #pragma unroll
        for (int mi = 0; mi < 2; mi++) {
            int m0 = warp_m * 32 + mi * 16;
            uint32_t aoff = ((m0 + (lane & 15)) * 40 + ks * 16 + ((lane >> 4) << 3)) * 2;
            ldsm_x4(ah[mi], abase_h + aoff);
            ldsm_x4(al[mi], abase_l + aoff);
        }
        uint32_t bh[4][2];
        #pragma unroll
        for (int nb = 0; nb < 2; nb++) {
            int n0 = warp_n * 32 + nb * 16;
            int krow = ks * 16 + ((lane >> 3) & 1) * 8 + (lane & 7);
            int ncol = n0 + (lane >> 4) * 8;
            uint32_t boff = (krow * 136 + ncol) * 2;
            uint32_t r0, r1, r2, r3;
            ldsm_x4t(r0, r1, r2, r3, bbase_h + boff);
            bh[nb * 2][0] = r0; bh[nb * 2][1] = r1; bh[nb * 2 + 1][0] = r2; bh[nb * 2 + 1][1] = r3;
        }
        #pragma unroll
        for (int mi = 0; mi < 2; mi++)
            #pragma unroll
            for (int ni = 0; ni < 4; ni++) {
                mma_f16(acc[mi][ni], ah[mi], bh[ni]);
                mma_f16(acc[mi][ni], al[mi], bh[ni]);
            }
    }
}

// layer GEMM: fp16 2-product, A resident (stride 136), B hi-only double buffer
__device__ __forceinline__ void compute_tile_fused(uint32_t sbase, int bbuf, int kpos,
                                                   int warp_m, int warp_n,
                                                   int lane, float (&acc)[2][8][4]) {
    uint32_t bbase_h = sbase + FB_OFF + bbuf * FB_BUF;
    #pragma unroll
    for (int ks = 0; ks < 2; ks++) {
        int kk = kpos + ks * 16;
        uint32_t ah[2][4], al[2][4];
        #pragma unroll
        for (int mi = 0; mi < 2; mi++) {
            int m0 = warp_m * 32 + mi * 16;
            uint32_t aoff = ((m0 + (lane & 15)) * 136 + kk + ((lane >> 4) << 3)) * 2;
            ldsm_x4(ah[mi], sbase + FA_H_OFF + aoff);
            ldsm_x4(al[mi], sbase + FA_L_OFF + aoff);
        }
        uint32_t bh[8][2];
        #pragma unroll
        for (int nb = 0; nb < 4; nb++) {
            int n0 = warp_n * 64 + nb * 16;
            int krow = ks * 16 + ((lane >> 3) & 1) * 8 + (lane & 7);
            int ncol = n0 + (lane >> 4) * 8;
            uint32_t boff = (krow * 136 + ncol) * 2;
            uint32_t r0, r1, r2, r3;
            ldsm_x4t(r0, r1, r2, r3, bbase_h + boff);
            bh[nb * 2][0] = r0; bh[nb * 2][1] = r1; bh[nb * 2 + 1][0] = r2; bh[nb * 2 + 1][1] = r3;
        }
        #pragma unroll
        for (int mi = 0; mi < 2; mi++)
            #pragma unroll
            for (int ni = 0; ni < 8; ni++) {
                mma_f16(acc[mi][ni], ah[mi], bh[ni]);
                mma_f16(acc[mi][ni], al[mi], bh[ni]);
            }
    }
}

// ------------------- GEMM 1: feature @ w_in (fp16 2-product) ------------------
__global__ __launch_bounds__(256, 2) void gemm_in_mma(
    const float* __restrict__ A, const float* __restrict__ bias, int M)
{
    extern __shared__ char smem[];
    uint32_t sbase = smem_to_u32(smem);
    const int tid = threadIdx.x, lane = tid & 31, wid = tid >> 5;
    const int warp_m = wid & 1, warp_n = wid >> 1;
    const int block_row = blockIdx.x * 64;

    float acc[2][4][4];
    #pragma unroll
    for (int a = 0; a < 2; a++)
        #pragma unroll
        for (int b = 0; b < 4; b++)
            #pragma unroll
            for (int c = 0; c < 4; c++) acc[a][b][c] = 0.f;

    float4 ra[2];
    uint4 rbh[2];
    fetch_a_f32_64(A, block_row, M, 0, ra);
    fetch_b_h(g_win_hf, 0, rbh);
    store_a_split_64(smem, 0, ra);
    store_b_64h(smem, 0, rbh);
    __syncthreads();

    const int NIT = DIN / 32;  // 24
    #pragma unroll 1
    for (int it = 0; it < NIT; it++) {
        if (it + 1 < NIT) {
            fetch_a_f32_64(A, block_row, M, (it + 1) * 32, ra);
            fetch_b_h(g_win_hf, (it + 1) * 32, rbh);
        }
        compute_tile_64(sbase, it & 1, warp_m, warp_n, lane, acc);
        if (it + 1 < NIT) {
            store_a_split_64(smem, (it + 1) & 1, ra);
            store_b_64h(smem, (it + 1) & 1, rbh);
        }
        __syncthreads();
    }

    const int g = lane >> 2, t = lane & 3;
    #pragma unroll
    for (int mi = 0; mi < 2; mi++) {
        #pragma unroll
        for (int ni = 0; ni < 4; ni++) {
            int col = warp_n * 32 + ni * 8 + t * 2;
            float b0 = __ldg(&bias[col]), b1 = __ldg(&bias[col + 1]);
            #pragma unroll
            for (int half = 0; half < 2; half++) {
                int row = block_row + warp_m * 32 + mi * 16 + g + half * 8;
                if (row >= M) continue;
                float v0 = acc[mi][ni][half * 2 + 0] + b0;
                float v1 = acc[mi][ni][half * 2 + 1] + b1;
                v0 = v0 >= 0.f ? v0 : LEAKY_SLOPE * v0;
                v1 = v1 >= 0.f ? v1 : LEAKY_SLOPE * v1;
                uint32_t h, l;
                split2_f16(v0, v1, h, l);
                *reinterpret_cast<uint32_t*>(g_xh + (size_t)row * H + col) = h;
                *reinterpret_cast<uint32_t*>(g_xl + (size_t)row * H + col) = l;
            }
        }
    }
}

// --------------- fused layer GEMM: z = x @ {W_r0, W_r1, W_root} --------------
__global__ __launch_bounds__(256, 2) void gemm_layer_fused(const float* __restrict__ b_conv, int M)
{
    extern __shared__ char smem[];
    uint32_t sbase = smem_to_u32(smem);
    const int tid = threadIdx.x, lane = tid & 31, wid = tid >> 5;
    const int warp_m = wid & 3, warp_n = wid >> 2;
    const int block_row = blockIdx.x * 128;

    #pragma unroll
    for (int i = 0; i < 8; i++) {
        int idx = tid + i * 256;
        int row = idx >> 4, cg = idx & 15;
        size_t so = (size_t)(block_row + row) * H + cg * 8;
        uint32_t off = (row * 136 + cg * 8) * 2;
        *reinterpret_cast<uint4*>(smem + FA_H_OFF + off) = *reinterpret_cast<const uint4*>(g_xh + so);
        *reinterpret_cast<uint4*>(smem + FA_L_OFF + off) = *reinterpret_cast<const uint4*>(g_xl + so);
    }
    uint4 rbh[2];
    fetch_b_h(g_wl_hf, 0, rbh);
    store_b_fused(smem, 0, rbh);
    __syncthreads();

    float acc[2][8][4];
    #pragma unroll
    for (int a = 0; a < 2; a++)
        #pragma unroll
        for (int b = 0; b < 8; b++)
            #pragma unroll
            for (int c = 0; c < 4; c++) acc[a][b][c] = 0.f;

    const int g = lane >> 2, t = lane & 3;

    #pragma unroll 1
    for (int q = 0; q < 12; q++) {
        int which = q >> 2, it = q & 3;
        if (q + 1 < 12) {
            int wn = (q + 1) >> 2, itn = (q + 1) & 3;
            fetch_b_h(g_wl_hf + (size_t)wn * H * H, itn * 32, rbh);
        }
        compute_tile_fused(sbase, q & 1, it * 32, warp_m, warp_n, lane, acc);
        if (q + 1 < 12)
            store_b_fused(smem, (q + 1) & 1, rbh);

        if (it == 3) {
            float* dst = (which < 2) ? (g_y + (size_t)which * NMAX * H) : g_root;
            const bool add_bias = (which == 2);
            #pragma unroll
            for (int mi = 0; mi < 2; mi++) {
                #pragma unroll
                for (int ni = 0; ni < 8; ni++) {
                    int col = warp_n * 64 + ni * 8 + t * 2;
                    float b0 = add_bias ? __ldg(&b_conv[col]) : 0.f;
                    float b1 = add_bias ? __ldg(&b_conv[col + 1]) : 0.f;
                    #pragma unroll
                    for (int half = 0; half < 2; half++) {
                        int row = block_row + warp_m * 32 + mi * 16 + g + half * 8;
                        if (row >= M) continue;
                        float v0 = acc[mi][ni][half * 2 + 0] + b0;
                        float v1 = acc[mi][ni][half * 2 + 1] + b1;
                        *reinterpret_cast<float2*>(dst + (size_t)row * H + col) = make_float2(v0, v1);
                    }
                }
            }
            #pragma unroll
            for (int a = 0; a < 2; a++)
                #pragma unroll
                for (int b = 0; b < 8; b++)
                    #pragma unroll
                    for (int c = 0; c < 4; c++) acc[a][b][c] = 0.f;
        }
        __syncthreads();
    }
}

// ---------------------- fused CSR aggregate + mean + root --------------------
__global__ __launch_bounds__(256) void agg_combine_kernel(
    int M, int last,
    const float* __restrict__ w_out, const float* __restrict__ b_out,
    float* __restrict__ out)
{
    int warp = (int)(((size_t)blockIdx.x * blockDim.x + threadIdx.x) >> 5);
    int lane = threadIdx.x & 31;
    if (warp >= M) return;

    size_t ridx = (size_t)warp * (H / 4) + lane;
    float4 o = reinterpret_cast<const float4*>(g_root)[ridx];

    #pragma unroll
    for (int t = 0; t < 2; t++) {
        int beg = g_off[t * NMAX + warp];
        int end = g_off[t * NMAX + warp + 1];
        int deg = end - beg;
        if (deg <= 0) continue;
        if (deg > EMAX) deg = EMAX;
        end = beg + deg;
        const float* yb = g_y + (size_t)t * NMAX * H;
        float4 s = make_float4(0.f, 0.f, 0.f, 0.f);
        for (int base = beg; base < end; base += 32) {
            int n = min(32, end - base);
            int idx = 0;
            if (lane < n) idx = g_esrc[base + lane];
            int j = 0;
            for (; j + 4 <= n; j += 4) {
                int s0 = __shfl_sync(0xFFFFFFFFu, idx, j);
                int s1 = __shfl_sync(0xFFFFFFFFu, idx, j + 1);
                int s2 = __shfl_sync(0xFFFFFFFFu, idx, j + 2);
                int s3 = __shfl_sync(0xFFFFFFFFu, idx, j + 3);
                float4 v0 = reinterpret_cast<const float4*>(yb + (size_t)s0 * H)[lane];
                float4 v1 = reinterpret_cast<const float4*>(yb + (size_t)s1 * H)[lane];
                float4 v2 = reinterpret_cast<const float4*>(yb + (size_t)s2 * H)[lane];
                float4 v3 = reinterpret_cast<const float4*>(yb + (size_t)s3 * H)[lane];
                s.x += v0.x + v1.x + v2.x + v3.x;
                s.y += v0.y + v1.y + v2.y + v3.y;
                s.z += v0.z + v1.z + v2.z + v3.z;
                s.w += v0.w + v1.w + v2.w + v3.w;
            }
            for (; j < n; j++) {
                int sj = __shfl_sync(0xFFFFFFFFu, idx, j);
                float4 v = reinterpret_cast<const float4*>(yb + (size_t)sj * H)[lane];
                s.x += v.x; s.y += v.y; s.z += v.z; s.w += v.w;
            }
        }
        float inv = 1.f / (float)deg;
        o.x += s.x * inv;
        o.y += s.y * inv;
        o.z += s.z * inv;
        o.w += s.w * inv;
    }

    if (!last) {
        uint32_t h0, l0, h1, l1;
        split2_f16(o.x, o.y, h0, l0);
        split2_f16(o.z, o.w, h1, l1);
        reinterpret_cast<uint2*>(g_xh)[ridx] = make_uint2(h0, h1);
        reinterpret_cast<uint2*>(g_xl)[ridx] = make_uint2(l0, l1);
    } else {
        float s0 = 0.f, s1 = 0.f, s2 = 0.f;
        int r = lane * 4;
        float xc[4] = {o.x, o.y, o.z, o.w};
        #pragma unroll
        for (int c = 0; c < 4; c++) {
            s0 = fmaf(xc[c], __ldg(&w_out[(r + c) * 3 + 0]), s0);
            s1 = fmaf(xc[c], __ldg(&w_out[(r + c) * 3 + 1]), s1);
            s2 = fmaf(xc[c], __ldg(&w_out[(r + c) * 3 + 2]), s2);
        }
        #pragma unroll
        for (int off = 16; off > 0; off >>= 1) {
            s0 += __shfl_xor_sync(0xFFFFFFFFu, s0, off);
            s1 += __shfl_xor_sync(0xFFFFFFFFu, s1, off);
            s2 += __shfl_xor_sync(0xFFFFFFFFu, s2, off);
        }
        if (lane == 0) {
            out[(size_t)warp * 3 + 0] = s0 + b_out[0];
            out[(size_t)warp * 3 + 1] = s1 + b_out[1];
            out[(size_t)warp * 3 + 2] = s2 + b_out[2];
        }
    }
}

// ------------------------------ launch glue -----------------------------------
extern "C" void kernel_launch(void* const* d_in, const int* in_sizes, int n_in,
                              void* d_out, int out_size) {
    const float* feature = (const float*)d_in[0];
    const void*  edge_index = d_in[1];
    const void*  edge_type  = d_in[2];
    const float* w_in   = (const float*)d_in[3];
    const float* b_in   = (const float*)d_in[4];
    const float* w_rel  = (const float*)d_in[5];
    const float* w_root = (const float*)d_in[6];
    const float* b_conv = (const float*)d_in[7];
    const float* w_out  = (const float*)d_in[8];
    const float* b_out  = (const float*)d_in[9];

    const int M = in_sizes[0] / DIN;      // 50000
    const int E = in_sizes[2];            // 600000
    const int tiles64  = (M + 63) / 64;   // 782
    const int tiles128 = (M + 127) / 128; // 391

    static cudaStream_t s2 = nullptr;
    static cudaEvent_t ev0 = nullptr, ev1 = nullptr;
    static bool attr_done = false;
    if (!attr_done) {
        cudaFuncSetAttribute(gemm_in_mma, cudaFuncAttributeMaxDynamicSharedMemorySize, I64_SMEM);
        cudaFuncSetAttribute(gemm_layer_fused, cudaFuncAttributeMaxDynamicSharedMemorySize, FUSED_SMEM);
        cudaStreamCreateWithFlags(&s2, cudaStreamNonBlocking);
        cudaEventCreateWithFlags(&ev0, cudaEventDisableTiming);
        cudaEventCreateWithFlags(&ev1, cudaEventDisableTiming);
        attr_done = true;
    }

    // Fork side stream for the CSR build (independent of GEMM chain)
    cudaEventRecord(ev0, 0);
    cudaStreamWaitEvent(s2, ev0, 0);

    // main chain: merged weight prep + input GEMM
    prep_weights_kernel<<<(DIN * H + 3 * H * H + 255) / 256, 256>>>(w_in, w_rel, w_root);
    zero_deg_detect_kernel<<<(KBKT + 255) / 256, 256, 0, s2>>>(edge_index, E);
    gemm_in_mma<<<tiles64, 256, I64_SMEM>>>(feature, b_in, M);

    // CSR build on side stream
    hist_kernel<<<(E + 255) / 256, 256, 0, s2>>>(edge_index, edge_type, E);
    scan1_kernel<<<NBLK, 1024, 0, s2>>>();
    scan2_kernel<<<1, 32, 0, s2>>>();
    scan3_kernel<<<NBLK, 1024, 0, s2>>>();
    fill_kernel<<<(E + 255) / 256, 256, 0, s2>>>(edge_index, edge_type, E);
    cudaEventRecord(ev1, s2);

    // layer 1 GEMM overlaps CSR tail; agg joins both chains
    gemm_layer_fused<<<tiles128, 256, FUSED_SMEM>>>(b_conv, M);
    cudaStreamWaitEvent(0, ev1, 0);
    agg_combine_kernel<<<(int)(((size_t)M * 32 + 255) / 256), 256>>>(
        M, 0, w_out, b_out, (float*)d_out);
    gemm_layer_fused<<<tiles128, 256, FUSED_SMEM>>>(b_conv, M);
    agg_combine_kernel<<<(int)(((size_t)M * 32 + 255) / 256), 256>>>(
        M, 1, w_out, b_out, (float*)d_out);
}

// round 17
// speedup vs baseline: 1.4282x; 1.0945x over previous
#include <cuda_runtime.h>
#include <cuda_bf16.h>
#include <cuda_fp16.h>
#include <cstdint>

// ---------------------------------------------------------------------------
// RGCN forward — fp16 2-product GEMMs + fp16 y storage (halved gather traffic):
//   h = leaky_relu(feature @ w_in + b_in)   gemm_in (64-row tiles)
//   CSR build on side stream
//   per layer: z = x @ [W_r0|W_r1|W_root]   fused layer GEMM (y stored fp16)
//              x' = root + sum_t mean(y_t[src]) warp gather (fp16 rows)
//   layer 2 agg fuses final GEMV.
// ---------------------------------------------------------------------------

#define NMAX 50176
#define DIN  768
#define H    128
#define LEAKY_SLOPE 0.01f
#define KBKT (2 * NMAX)
#define NBLK (KBKT / 1024)
#define EMAX (1 << 20)

// ------------------------------ device scratch ------------------------------
__device__ __align__(16) __half g_y[(size_t)2 * NMAX * H];        // y in fp16
__device__ __align__(16) float g_root[(size_t)NMAX * H];          // root fp32
__device__ int g_idx32;

__device__ __align__(16) __half g_xh[(size_t)NMAX * H];           // x hi (fp16)
__device__ __align__(16) __half g_xl[(size_t)NMAX * H];           // x lo (fp16)
__device__ __align__(16) __half g_win_hf[(size_t)DIN * H];        // w_in (fp16 hi)
__device__ __align__(16) __half g_wl_hf[(size_t)3 * H * H];       // layer W (fp16 hi)

// CSR
__device__ int g_deg[KBKT];
__device__ int g_scan[KBKT];
__device__ int g_bsum[NBLK];
__device__ int g_off[KBKT + 1];
__device__ int g_cur[KBKT];
__device__ int g_esrc[EMAX];

// ------------------------------- helpers ------------------------------------
__device__ __forceinline__ uint32_t smem_to_u32(const void* p) {
    uint32_t a;
    asm("{ .reg .u64 t; cvta.to.shared.u64 t, %1; cvt.u32.u64 %0, t; }" : "=r"(a) : "l"(p));
    return a;
}
__device__ __forceinline__ void split2_f16(float a, float b, uint32_t& h, uint32_t& l) {
    __half ha = __float2half(a), hb = __float2half(b);
    __half la = __float2half(a - __half2float(ha));
    __half lb = __float2half(b - __half2float(hb));
    __half2 hp = __halves2half2(ha, hb);
    __half2 lp = __halves2half2(la, lb);
    h = *reinterpret_cast<uint32_t*>(&hp);
    l = *reinterpret_cast<uint32_t*>(&lp);
}
__device__ __forceinline__ void ldsm_x4(uint32_t (&r)[4], uint32_t addr) {
    asm volatile("ldmatrix.sync.aligned.m8n8.x4.shared.b16 {%0,%1,%2,%3}, [%4];"
                 : "=r"(r[0]), "=r"(r[1]), "=r"(r[2]), "=r"(r[3]) : "r"(addr));
}
__device__ __forceinline__ void ldsm_x4t(uint32_t& r0, uint32_t& r1, uint32_t& r2, uint32_t& r3, uint32_t addr) {
    asm volatile("ldmatrix.sync.aligned.m8n8.x4.trans.shared.b16 {%0,%1,%2,%3}, [%4];"
                 : "=r"(r0), "=r"(r1), "=r"(r2), "=r"(r3) : "r"(addr));
}
__device__ __forceinline__ void mma_f16(float (&d)[4], const uint32_t (&a)[4], const uint32_t (&b)[2]) {
    asm volatile(
        "mma.sync.aligned.m16n8k16.row.col.f32.f16.f16.f32 "
        "{%0,%1,%2,%3}, {%4,%5,%6,%7}, {%8,%9}, {%0,%1,%2,%3};"
        : "+f"(d[0]), "+f"(d[1]), "+f"(d[2]), "+f"(d[3])
        : "r"(a[0]), "r"(a[1]), "r"(a[2]), "r"(a[3]), "r"(b[0]), "r"(b[1]));
}

// ---------------- smem layout: gemm_in 64-row tiles (fp16, no B-lo) ----------
#define I64_AH   0
#define I64_AL   10240
#define I64_BH   20480
#define I64_ABUF 5120
#define I64_BBUF 8704
#define I64_SMEM 37888

// ---------------- smem layout: fused layer GEMM (fp16, B hi only) ------------
#define FA_H_OFF 0
#define FA_L_OFF 34816
#define FB_OFF   69632
#define FB_BUF   8704
#define FUSED_SMEM 87040

// --------------------------- index dtype handling ---------------------------
__device__ __forceinline__ int ld_idx(const void* p, long long i) {
    if (g_idx32) return ((const int*)p)[i];
    return (int)((const long long*)p)[i];
}

// -------------------- CSR build (detect fused into zero) --------------------
__global__ void zero_deg_detect_kernel(const void* ei, int E) {
    int i = blockIdx.x * blockDim.x + threadIdx.x;
    if (i < KBKT) g_deg[i] = 0;
    if (i == 0) {
        const long long* p = (const long long*)ei;
        int n = E < 256 ? E : 256;
        int is32 = 0;
        for (int k = 0; k < n; k++) {
            long long v = p[k];
            if (v < 0 || v >= (long long)NMAX) { is32 = 1; break; }
        }
        g_idx32 = is32;
    }
}
__global__ void hist_kernel(const void* ei, const void* et, int E) {
    int e = blockIdx.x * blockDim.x + threadIdx.x;
    if (e >= E) return;
    int t   = ld_idx(et, e);
    int dst = ld_idx(ei, (long long)E + e);
    atomicAdd(&g_deg[t * NMAX + dst], 1);
}
__global__ __launch_bounds__(1024) void scan1_kernel() {
    int i = blockIdx.x * 1024 + threadIdx.x;
    int lane = threadIdx.x & 31, w = threadIdx.x >> 5;
    int x = g_deg[i];
    #pragma unroll
    for (int off = 1; off < 32; off <<= 1) {
        int y = __shfl_up_sync(0xFFFFFFFFu, x, off);
        if (lane >= off) x += y;
    }
    __shared__ int wsum[32];
    if (lane == 31) wsum[w] = x;
    __syncthreads();
    if (w == 0) {
        int s = wsum[lane];
        #pragma unroll
        for (int off = 1; off < 32; off <<= 1) {
            int y = __shfl_up_sync(0xFFFFFFFFu, s, off);
            if (lane >= off) s += y;
        }
        wsum[lane] = s;
    }
    __syncthreads();
    if (w > 0) x += wsum[w - 1];
    g_scan[i] = x;
    if (threadIdx.x == 1023) g_bsum[blockIdx.x] = x;
}
__global__ __launch_bounds__(32) void scan2_kernel() {
    int lane = threadIdx.x;
    int carry = 0;
    for (int base = 0; base < NBLK; base += 32) {
        int i = base + lane;
        int x = (i < NBLK) ? g_bsum[i] : 0;
        #pragma unroll
        for (int off = 1; off < 32; off <<= 1) {
            int y = __shfl_up_sync(0xFFFFFFFFu, x, off);
            if (lane >= off) x += y;
        }
        x += carry;
        if (i < NBLK) g_bsum[i] = x;
        carry = __shfl_sync(0xFFFFFFFFu, x, 31);
    }
}
__global__ __launch_bounds__(1024) void scan3_kernel() {
    int i = blockIdx.x * 1024 + threadIdx.x;
    int blk = blockIdx.x;
    int off = g_scan[i] - g_deg[i] + (blk > 0 ? g_bsum[blk - 1] : 0);
    g_off[i] = off;
    g_cur[i] = off;
    if (i == KBKT - 1) g_off[KBKT] = g_bsum[NBLK - 1];
}
__global__ void fill_kernel(const void* ei, const void* et, int E) {
    int e = blockIdx.x * blockDim.x + threadIdx.x;
    if (e >= E) return;
    int src = ld_idx(ei, e);
    int dst = ld_idx(ei, (long long)E + e);
    int t   = ld_idx(et, e);
    int pos = atomicAdd(&g_cur[t * NMAX + dst], 1);
    if (pos >= 0 && pos < EMAX) g_esrc[pos] = src;
}

// ---------------- weight prep, single merged kernel --------------------------
__global__ void prep_weights_kernel(const float* __restrict__ w_in,
                                    const float* __restrict__ w_rel,
                                    const float* __restrict__ w_root) {
    int idx = blockIdx.x * blockDim.x + threadIdx.x;
    const int NIN = DIN * H;           // 98304
    const int NL  = 3 * H * H;         // 49152
    if (idx < NIN) {
        g_win_hf[idx] = __float2half(w_in[idx]);
    } else if (idx < NIN + NL) {
        int j = idx - NIN;
        float v = (j < 2 * H * H) ? w_rel[j] : w_root[j - 2 * H * H];
        g_wl_hf[j] = __float2half(v);
    }
}

// ------------------------------ tile fetch/store -----------------------------
__device__ __forceinline__ void fetch_a_f32_64(const float* __restrict__ A, int block_row, int M,
                                               int k0, float4 (&r)[2]) {
    int tid = threadIdx.x;
    #pragma unroll
    for (int i = 0; i < 2; i++) {
        int idx = tid + i * 256;
        int row = idx >> 3, c4 = idx & 7;
        int gr = block_row + row; if (gr >= M) gr = M - 1;
        r[i] = *reinterpret_cast<const float4*>(A + (size_t)gr * DIN + k0 + c4 * 4);
    }
}
__device__ __forceinline__ void store_a_split_64(char* smem, int buf, const float4 (&r)[2]) {
    int tid = threadIdx.x;
    #pragma unroll
    for (int i = 0; i < 2; i++) {
        int idx = tid + i * 256;
        int row = idx >> 3, c4 = idx & 7;
        uint32_t h0, l0, h1, l1;
        split2_f16(r[i].x, r[i].y, h0, l0);
        split2_f16(r[i].z, r[i].w, h1, l1);
        uint32_t off = (row * 40 + c4 * 4) * 2;
        *reinterpret_cast<uint2*>(smem + I64_AH + buf * I64_ABUF + off) = make_uint2(h0, h1);
        *reinterpret_cast<uint2*>(smem + I64_AL + buf * I64_ABUF + off) = make_uint2(l0, l1);
    }
}
__device__ __forceinline__ void fetch_b_h(const __half* __restrict__ bh, int k0, uint4 (&rh)[2]) {
    int tid = threadIdx.x;
    #pragma unroll
    for (int i = 0; i < 2; i++) {
        int idx = tid + i * 256;
        int row = idx >> 4, col = (idx & 15) * 8;
        size_t so = (size_t)(k0 + row) * H + col;
        rh[i] = *reinterpret_cast<const uint4*>(bh + so);
    }
}
__device__ __forceinline__ void store_b_64h(char* smem, int buf, const uint4 (&rh)[2]) {
    int tid = threadIdx.x;
    #pragma unroll
    for (int i = 0; i < 2; i++) {
        int idx = tid + i * 256;
        int row = idx >> 4, col = (idx & 15) * 8;
        uint32_t off = (row * 136 + col) * 2;
        *reinterpret_cast<uint4*>(smem + I64_BH + buf * I64_BBUF + off) = rh[i];
    }
}
__device__ __forceinline__ void store_b_fused(char* smem, int buf, const uint4 (&rh)[2]) {
    int tid = threadIdx.x;
    #pragma unroll
    for (int i = 0; i < 2; i++) {
        int idx = tid + i * 256;
        int row = idx >> 4, col = (idx & 15) * 8;
        uint32_t off = (row * 136 + col) * 2;
        *reinterpret_cast<uint4*>(smem + FB_OFF + buf * FB_BUF + off) = rh[i];
    }
}

// ------------------------------- compute cores --------------------------------
__device__ __forceinline__ void compute_tile_64(uint32_t sbase, int buf, int warp_m, int warp_n,
                                                int lane, float (&acc)[2][4][4]) {
    uint32_t abase_h = sbase + I64_AH + buf * I64_ABUF;
    uint32_t abase_l = sbase + I64_AL + buf * I64_ABUF;
    uint32_t bbase_h = sbase + I64_BH + buf * I64_BBUF;
    #pragma unroll
    for (int ks = 0; ks < 2; ks++) {
        uint32_t ah[2][4], al[2][4];
        #pragma unroll
        for (int mi = 0; mi < 2; mi++) {
            int m0 = warp_m * 32 + mi * 16;
            uint32_t aoff = ((m0 + (lane & 15)) * 40 + ks * 16 + ((lane >> 4) << 3)) * 2;
            ldsm_x4(ah[mi], abase_h + aoff);
            ldsm_x4(al[mi], abase_l + aoff);
        }
        uint32_t bh[4][2];
        #pragma unroll
        for (int nb = 0; nb < 2; nb++) {
            int n0 = warp_n * 32 + nb * 16;
            int krow = ks * 16 + ((lane >> 3) & 1) * 8 + (lane & 7);
            int ncol = n0 + (lane >> 4) * 8;
            uint32_t boff = (krow * 136 + ncol) * 2;
            uint32_t r0, r1, r2, r3;
            ldsm_x4t(r0, r1, r2, r3, bbase_h + boff);
            bh[nb * 2][0] = r0; bh[nb * 2][1] = r1; bh[nb * 2 + 1][0] = r2; bh[nb * 2 + 1][1] = r3;
        }
        #pragma unroll
        for (int mi = 0; mi < 2; mi++)
            #pragma unroll
            for (int ni = 0; ni < 4; ni++) {
                mma_f16(acc[mi][ni], ah[mi], bh[ni]);
                mma_f16(acc[mi][ni], al[mi], bh[ni]);
            }
    }
}

__device__ __forceinline__ void compute_tile_fused(uint32_t sbase, int bbuf, int kpos,
                                                   int warp_m, int warp_n,
                                                   int lane, float (&acc)[2][8][4]) {
    uint32_t bbase_h = sbase + FB_OFF + bbuf * FB_BUF;
    #pragma unroll
    for (int ks = 0; ks < 2; ks++) {
        int kk = kpos + ks * 16;
        uint32_t ah[2][4], al[2][4];
        #pragma unroll
        for (int mi = 0; mi < 2; mi++) {
            int m0 = warp_m * 32 + mi * 16;
            uint32_t aoff = ((m0 + (lane & 15)) * 136 + kk + ((lane >> 4) << 3)) * 2;
            ldsm_x4(ah[mi], sbase + FA_H_OFF + aoff);
            ldsm_x4(al[mi], sbase + FA_L_OFF + aoff);
        }
        uint32_t bh[8][2];
        #pragma unroll
        for (int nb = 0; nb < 4; nb++) {
            int n0 = warp_n * 64 + nb * 16;
            int krow = ks * 16 + ((lane >> 3) & 1) * 8 + (lane & 7);
            int ncol = n0 + (lane >> 4) * 8;
            uint32_t boff = (krow * 136 + ncol) * 2;
            uint32_t r0, r1, r2, r3;
            ldsm_x4t(r0, r1, r2, r3, bbase_h + boff);
            bh[nb * 2][0] = r0; bh[nb * 2][1] = r1; bh[nb * 2 + 1][0] = r2; bh[nb * 2 + 1][1] = r3;
        }
        #pragma unroll
        for (int mi = 0; mi < 2; mi++)
            #pragma unroll
            for (int ni = 0; ni < 8; ni++) {
                mma_f16(acc[mi][ni], ah[mi], bh[ni]);
                mma_f16(acc[mi][ni], al[mi], bh[ni]);
            }
    }
}

// ------------------- GEMM 1: feature @ w_in (fp16 2-product) ------------------
__global__ __launch_bounds__(256, 2) void gemm_in_mma(
    const float* __restrict__ A, const float* __restrict__ bias, int M)
{
    extern __shared__ char smem[];
    uint32_t sbase = smem_to_u32(smem);
    const int tid = threadIdx.x, lane = tid & 31, wid = tid >> 5;
    const int warp_m = wid & 1, warp_n = wid >> 1;
    const int block_row = blockIdx.x * 64;

    float acc[2][4][4];
    #pragma unroll
    for (int a = 0; a < 2; a++)
        #pragma unroll
        for (int b = 0; b < 4; b++)
            #pragma unroll
            for (int c = 0; c < 4; c++) acc[a][b][c] = 0.f;

    float4 ra[2];
    uint4 rbh[2];
    fetch_a_f32_64(A, block_row, M, 0, ra);
    fetch_b_h(g_win_hf, 0, rbh);
    store_a_split_64(smem, 0, ra);
    store_b_64h(smem, 0, rbh);
    __syncthreads();

    const int NIT = DIN / 32;  // 24
    #pragma unroll 1
    for (int it = 0; it < NIT; it++) {
        if (it + 1 < NIT) {
            fetch_a_f32_64(A, block_row, M, (it + 1) * 32, ra);
            fetch_b_h(g_win_hf, (it + 1) * 32, rbh);
        }
        compute_tile_64(sbase, it & 1, warp_m, warp_n, lane, acc);
        if (it + 1 < NIT) {
            store_a_split_64(smem, (it + 1) & 1, ra);
            store_b_64h(smem, (it + 1) & 1, rbh);
        }
        __syncthreads();
    }

    const int g = lane >> 2, t = lane & 3;
    #pragma unroll
    for (int mi = 0; mi < 2; mi++) {
        #pragma unroll
        for (int ni = 0; ni < 4; ni++) {
            int col = warp_n * 32 + ni * 8 + t * 2;
            float b0 = __ldg(&bias[col]), b1 = __ldg(&bias[col + 1]);
            #pragma unroll
            for (int half = 0; half < 2; half++) {
                int row = block_row + warp_m * 32 + mi * 16 + g + half * 8;
                if (row >= M) continue;
                float v0 = acc[mi][ni][half * 2 + 0] + b0;
                float v1 = acc[mi][ni][half * 2 + 1] + b1;
                v0 = v0 >= 0.f ? v0 : LEAKY_SLOPE * v0;
                v1 = v1 >= 0.f ? v1 : LEAKY_SLOPE * v1;
                uint32_t h, l;
                split2_f16(v0, v1, h, l);
                *reinterpret_cast<uint32_t*>(g_xh + (size_t)row * H + col) = h;
                *reinterpret_cast<uint32_t*>(g_xl + (size_t)row * H + col) = l;
            }
        }
    }
}

// --------------- fused layer GEMM: z = x @ {W_r0, W_r1, W_root} --------------
// y (which<2) stored fp16; root stored fp32.
__global__ __launch_bounds__(256, 2) void gemm_layer_fused(const float* __restrict__ b_conv, int M)
{
    extern __shared__ char smem[];
    uint32_t sbase = smem_to_u32(smem);
    const int tid = threadIdx.x, lane = tid & 31, wid = tid >> 5;
    const int warp_m = wid & 3, warp_n = wid >> 2;
    const int block_row = blockIdx.x * 128;

    #pragma unroll
    for (int i = 0; i < 8; i++) {
        int idx = tid + i * 256;
        int row = idx >> 4, cg = idx & 15;
        size_t so = (size_t)(block_row + row) * H + cg * 8;
        uint32_t off = (row * 136 + cg * 8) * 2;
        *reinterpret_cast<uint4*>(smem + FA_H_OFF + off) = *reinterpret_cast<const uint4*>(g_xh + so);
        *reinterpret_cast<uint4*>(smem + FA_L_OFF + off) = *reinterpret_cast<const uint4*>(g_xl + so);
    }
    uint4 rbh[2];
    fetch_b_h(g_wl_hf, 0, rbh);
    store_b_fused(smem, 0, rbh);
    __syncthreads();

    float acc[2][8][4];
    #pragma unroll
    for (int a = 0; a < 2; a++)
        #pragma unroll
        for (int b = 0; b < 8; b++)
            #pragma unroll
            for (int c = 0; c < 4; c++) acc[a][b][c] = 0.f;

    const int g = lane >> 2, t = lane & 3;

    #pragma unroll 1
    for (int q = 0; q < 12; q++) {
        int which = q >> 2, it = q & 3;
        if (q + 1 < 12) {
            int wn = (q + 1) >> 2, itn = (q + 1) & 3;
            fetch_b_h(g_wl_hf + (size_t)wn * H * H, itn * 32, rbh);
        }
        compute_tile_fused(sbase, q & 1, it * 32, warp_m, warp_n, lane, acc);
        if (q + 1 < 12)
            store_b_fused(smem, (q + 1) & 1, rbh);

        if (it == 3) {
            const bool is_root = (which == 2);
            __half* ydst = g_y + (size_t)which * NMAX * H;   // used when !is_root
            #pragma unroll
            for (int mi = 0; mi < 2; mi++) {
                #pragma unroll
                for (int ni = 0; ni < 8; ni++) {
                    int col = warp_n * 64 + ni * 8 + t * 2;
                    float b0 = is_root ? __ldg(&b_conv[col]) : 0.f;
                    float b1 = is_root ? __ldg(&b_conv[col + 1]) : 0.f;
                    #pragma unroll
                    for (int half = 0; half < 2; half++) {
                        int row = block_row + warp_m * 32 + mi * 16 + g + half * 8;
                        if (row >= M) continue;
                        float v0 = acc[mi][ni][half * 2 + 0] + b0;
                        float v1 = acc[mi][ni][half * 2 + 1] + b1;
                        if (is_root) {
                            *reinterpret_cast<float2*>(g_root + (size_t)row * H + col) = make_float2(v0, v1);
                        } else {
                            __half2 hv = __floats2half2_rn(v0, v1);
                            *reinterpret_cast<__half2*>(ydst + (size_t)row * H + col) = hv;
                        }
                    }
                }
            }
            #pragma unroll
            for (int a = 0; a < 2; a++)
                #pragma unroll
                for (int b = 0; b < 8; b++)
                    #pragma unroll
                    for (int c = 0; c < 4; c++) acc[a][b][c] = 0.f;
        }
        __syncthreads();
    }
}

// ---------------------- fused CSR aggregate + mean + root --------------------
// One warp per node; y rows are fp16 (uint2 = 4 halves per lane).
__global__ __launch_bounds__(256) void agg_combine_kernel(
    int M, int last,
    const float* __restrict__ w_out, const float* __restrict__ b_out,
    float* __restrict__ out)
{
    int warp = (int)(((size_t)blockIdx.x * blockDim.x + threadIdx.x) >> 5);
    int lane = threadIdx.x & 31;
    if (warp >= M) return;

    size_t ridx = (size_t)warp * (H / 4) + lane;
    float4 o = reinterpret_cast<const float4*>(g_root)[ridx];

    #pragma unroll
    for (int t = 0; t < 2; t++) {
        int beg = g_off[t * NMAX + warp];
        int end = g_off[t * NMAX + warp + 1];
        int deg = end - beg;
        if (deg <= 0) continue;
        if (deg > EMAX) deg = EMAX;
        end = beg + deg;
        const __half* yb = g_y + (size_t)t * NMAX * H;
        float4 s = make_float4(0.f, 0.f, 0.f, 0.f);
        for (int base = beg; base < end; base += 32) {
            int n = min(32, end - base);
            int idx = 0;
            if (lane < n) idx = g_esrc[base + lane];
            int j = 0;
            for (; j + 4 <= n; j += 4) {
                uint2 u[4];
                #pragma unroll
                for (int q = 0; q < 4; q++) {
                    int sj = __shfl_sync(0xFFFFFFFFu, idx, j + q);
                    u[q] = *reinterpret_cast<const uint2*>(yb + (size_t)sj * H + lane * 4);
                }
                #pragma unroll
                for (int q = 0; q < 4; q++) {
                    float2 f0 = __half22float2(*reinterpret_cast<__half2*>(&u[q].x));
                    float2 f1 = __half22float2(*reinterpret_cast<__half2*>(&u[q].y));
                    s.x += f0.x; s.y += f0.y; s.z += f1.x; s.w += f1.y;
                }
            }
            for (; j < n; j++) {
                int sj = __shfl_sync(0xFFFFFFFFu, idx, j);
                uint2 u = *reinterpret_cast<const uint2*>(yb + (size_t)sj * H + lane * 4);
                float2 f0 = __half22float2(*reinterpret_cast<__half2*>(&u.x));
                float2 f1 = __half22float2(*reinterpret_cast<__half2*>(&u.y));
                s.x += f0.x; s.y += f0.y; s.z += f1.x; s.w += f1.y;
            }
        }
        float inv = 1.f / (float)deg;
        o.x += s.x * inv;
        o.y += s.y * inv;
        o.z += s.z * inv;
        o.w += s.w * inv;
    }

    if (!last) {
        uint32_t h0, l0, h1, l1;
        split2_f16(o.x, o.y, h0, l0);
        split2_f16(o.z, o.w, h1, l1);
        reinterpret_cast<uint2*>(g_xh)[ridx] = make_uint2(h0, h1);
        reinterpret_cast<uint2*>(g_xl)[ridx] = make_uint2(l0, l1);
    } else {
        float s0 = 0.f, s1 = 0.f, s2 = 0.f;
        int r = lane * 4;
        float xc[4] = {o.x, o.y, o.z, o.w};
        #pragma unroll
        for (int c = 0; c < 4; c++) {
            s0 = fmaf(xc[c], __ldg(&w_out[(r + c) * 3 + 0]), s0);
            s1 = fmaf(xc[c], __ldg(&w_out[(r + c) * 3 + 1]), s1);
            s2 = fmaf(xc[c], __ldg(&w_out[(r + c) * 3 + 2]), s2);
        }
        #pragma unroll
        for (int off = 16; off > 0; off >>= 1) {
            s0 += __shfl_xor_sync(0xFFFFFFFFu, s0, off);
            s1 += __shfl_xor_sync(0xFFFFFFFFu, s1, off);
            s2 += __shfl_xor_sync(0xFFFFFFFFu, s2, off);
        }
        if (lane == 0) {
            out[(size_t)warp * 3 + 0] = s0 + b_out[0];
            out[(size_t)warp * 3 + 1] = s1 + b_out[1];
            out[(size_t)warp * 3 + 2] = s2 + b_out[2];
        }
    }
}

// ------------------------------ launch glue -----------------------------------
extern "C" void kernel_launch(void* const* d_in, const int* in_sizes, int n_in,
                              void* d_out, int out_size) {
    const float* feature = (const float*)d_in[0];
    const void*  edge_index = d_in[1];
    const void*  edge_type  = d_in[2];
    const float* w_in   = (const float*)d_in[3];
    const float* b_in   = (const float*)d_in[4];
    const float* w_rel  = (const float*)d_in[5];
    const float* w_root = (const float*)d_in[6];
    const float* b_conv = (const float*)d_in[7];
    const float* w_out  = (const float*)d_in[8];
    const float* b_out  = (const float*)d_in[9];

    const int M = in_sizes[0] / DIN;      // 50000
    const int E = in_sizes[2];            // 600000
    const int tiles64  = (M + 63) / 64;   // 782
    const int tiles128 = (M + 127) / 128; // 391

    static cudaStream_t s2 = nullptr;
    static cudaEvent_t ev0 = nullptr, ev1 = nullptr;
    static bool attr_done = false;
    if (!attr_done) {
        cudaFuncSetAttribute(gemm_in_mma, cudaFuncAttributeMaxDynamicSharedMemorySize, I64_SMEM);
        cudaFuncSetAttribute(gemm_layer_fused, cudaFuncAttributeMaxDynamicSharedMemorySize, FUSED_SMEM);
        cudaStreamCreateWithFlags(&s2, cudaStreamNonBlocking);
        cudaEventCreateWithFlags(&ev0, cudaEventDisableTiming);
        cudaEventCreateWithFlags(&ev1, cudaEventDisableTiming);
        attr_done = true;
    }

    // Fork side stream for the CSR build (independent of GEMM chain)
    cudaEventRecord(ev0, 0);
    cudaStreamWaitEvent(s2, ev0, 0);

    // main chain: merged weight prep + input GEMM
    prep_weights_kernel<<<(DIN * H + 3 * H * H + 255) / 256, 256>>>(w_in, w_rel, w_root);
    zero_deg_detect_kernel<<<(KBKT + 255) / 256, 256, 0, s2>>>(edge_index, E);
    gemm_in_mma<<<tiles64, 256, I64_SMEM>>>(feature, b_in, M);

    // CSR build on side stream
    hist_kernel<<<(E + 255) / 256, 256, 0, s2>>>(edge_index, edge_type, E);
    scan1_kernel<<<NBLK, 1024, 0, s2>>>();
    scan2_kernel<<<1, 32, 0, s2>>>();
    scan3_kernel<<<NBLK, 1024, 0, s2>>>();
    fill_kernel<<<(E + 255) / 256, 256, 0, s2>>>(edge_index, edge_type, E);
    cudaEventRecord(ev1, s2);

    // layer 1 GEMM overlaps CSR tail; agg joins both chains
    gemm_layer_fused<<<tiles128, 256, FUSED_SMEM>>>(b_conv, M);
    cudaStreamWaitEvent(0, ev1, 0);
    agg_combine_kernel<<<(int)(((size_t)M * 32 + 255) / 256), 256>>>(
        M, 0, w_out, b_out, (float*)d_out);
    gemm_layer_fused<<<tiles128, 256, FUSED_SMEM>>>(b_conv, M);
    agg_combine_kernel<<<(int)(((size_t)M * 32 + 255) / 256), 256>>>(
        M, 1, w_out, b_out, (float*)d_out);
}